// round 11
// baseline (speedup 1.0000x reference)
#include <cuda_runtime.h>
#include <cuda_bf16.h>
#include <math.h>

#define TT 256
#define BB 128
#define CC 9
#define MM (TT*BB)      // 32768 rows

typedef __nv_bfloat16 bf16;

// ---------------- scratch (static device globals; no allocs) ----------------
__device__ bf16  g_X0b[(size_t)MM*512];       // layer0 input, bf16 (T,B,512)
__device__ bf16  g_HA0[(size_t)MM*512];       // layer0 h fwd (T,B,512)
__device__ bf16  g_HA1[(size_t)MM*512];       // layer0 h bwd
__device__ bf16  g_HB0[(size_t)MM*512];       // layer1 h fwd
__device__ bf16  g_HB1[(size_t)MM*512];       // layer1 h bwd
// PRE scan-major: [dir][jb(64)][t*B][32]  (gate*8 + jj within 32)
__device__ float g_PRE[(size_t)2*64*MM*32];
__device__ bf16  g_WI0b[4096*512];            // w_ih_l0 bf16
__device__ bf16  g_WI1b[(size_t)4096*1024];   // w_ih_l1 bf16
__device__ bf16  g_WH0b[2*2048*512];          // w_hh_l0 bf16
__device__ bf16  g_WH1b[2*2048*512];          // w_hh_l1 bf16
__device__ float g_EM[(size_t)MM*CC];
__device__ float g_LLH[BB];
// per-block per-half done flags: [layer][dir][step][half][block*32] (128B apart)
__device__ unsigned g_flags[2][2][TT][2][64*32];

__device__ __forceinline__ float fsig(float x){ return 1.0f/(1.0f+__expf(-x)); }
__device__ __forceinline__ float ftanh(float x){
    float ax = fabsf(x);
    float t = __expf(-2.0f*ax);
    float r = (1.0f - t)/(1.0f + t);
    return copysignf(r, x);
}

// ---------------- PTX helpers ----------------
__device__ __forceinline__ unsigned su32(const void* p){ return (unsigned)__cvta_generic_to_shared(p); }
__device__ __forceinline__ void cp16(unsigned s, const void* g){
    asm volatile("cp.async.cg.shared.global [%0], [%1], 16;\n" :: "r"(s), "l"(g));
}
__device__ __forceinline__ void cpcommit(){ asm volatile("cp.async.commit_group;\n"); }
template<int N> __device__ __forceinline__ void cpwait(){ asm volatile("cp.async.wait_group %0;\n"::"n"(N)); }
__device__ __forceinline__ void ldsm4(unsigned &r0, unsigned &r1, unsigned &r2, unsigned &r3, unsigned addr){
    asm volatile("ldmatrix.sync.aligned.m8n8.x4.shared.b16 {%0,%1,%2,%3}, [%4];\n"
        : "=r"(r0),"=r"(r1),"=r"(r2),"=r"(r3) : "r"(addr));
}
__device__ __forceinline__ void ldsm2(unsigned &r0, unsigned &r1, unsigned addr){
    asm volatile("ldmatrix.sync.aligned.m8n8.x2.shared.b16 {%0,%1}, [%2];\n"
        : "=r"(r0),"=r"(r1) : "r"(addr));
}
__device__ __forceinline__ void mma16816(float* c, const unsigned* a, unsigned b0, unsigned b1){
    asm volatile("mma.sync.aligned.m16n8k16.row.col.f32.bf16.bf16.f32 "
        "{%0,%1,%2,%3}, {%4,%5,%6,%7}, {%8,%9}, {%0,%1,%2,%3};\n"
        : "+f"(c[0]),"+f"(c[1]),"+f"(c[2]),"+f"(c[3])
        : "r"(a[0]),"r"(a[1]),"r"(a[2]),"r"(a[3]),"r"(b0),"r"(b1));
}
__device__ __forceinline__ void st_release(unsigned* p, unsigned v){
    asm volatile("st.release.gpu.global.u32 [%0], %1;" :: "l"(p), "r"(v) : "memory");
}
__device__ __forceinline__ unsigned load_acq(const unsigned* p){
    unsigned v;
    asm volatile("ld.acquire.gpu.global.u32 %0, [%1];" : "=r"(v) : "l"(p) : "memory");
    return v;
}
__device__ __forceinline__ void mbar_init(unsigned m, unsigned cnt){
    asm volatile("mbarrier.init.shared.b64 [%0], %1;" :: "r"(m), "r"(cnt) : "memory");
}
__device__ __forceinline__ void mbar_expect(unsigned m, unsigned bytes){
    asm volatile("mbarrier.arrive.expect_tx.shared.b64 _, [%0], %1;" :: "r"(m), "r"(bytes) : "memory");
}
__device__ __forceinline__ void bulkcp(unsigned dst, const void* src, unsigned bytes, unsigned m){
    asm volatile("cp.async.bulk.shared::cta.global.mbarrier::complete_tx::bytes [%0], [%1], %2, [%3];"
        :: "r"(dst), "l"(src), "r"(bytes), "r"(m) : "memory");
}
__device__ __forceinline__ void mbar_wait(unsigned m, unsigned parity){
    asm volatile(
        "{\n\t.reg .pred P;\n\t"
        "WL%=:\n\t"
        "mbarrier.try_wait.parity.acquire.cta.shared::cta.b64 P, [%0], %1, 0x989680;\n\t"
        "@P bra WD%=;\n\t"
        "bra WL%=;\n\t"
        "WD%=:\n\t}"
        :: "r"(m), "r"(parity) : "memory");
}
__device__ __forceinline__ void bar_named(int id, int nthreads){
    asm volatile("bar.sync %0, %1;" :: "r"(id), "r"(nthreads) : "memory");
}

// ---------------- reset flags (once per launch; graph-replay safe) ----------------
// total slots = 2*2*256*2*64 = 131072 ; grid 2048 x 64 threads
__global__ void reset_flags(){
    unsigned slot = blockIdx.x*64u + threadIdx.x;
    ((unsigned*)g_flags)[slot*32u] = 0u;
}

// ---------------- embedding lookup + norm clip -> bf16 ----------------
__global__ void embed_kernel(const int* __restrict__ x, const float* __restrict__ embed)
{
    int r = blockIdx.x;            // r = t*BB + b
    int t = r >> 7;
    int b = r & 127;
    int v = x[b*TT + t];
    const float* e = embed + (size_t)v * 512;
    int tid = threadIdx.x;         // 128
    float4 ev = ((const float4*)e)[tid];
    float ss = ev.x*ev.x + ev.y*ev.y + ev.z*ev.z + ev.w*ev.w;
    #pragma unroll
    for (int o = 16; o; o >>= 1) ss += __shfl_xor_sync(0xffffffffu, ss, o);
    __shared__ float sred[4];
    if ((tid & 31) == 0) sred[tid>>5] = ss;
    __syncthreads();
    float nrm = sqrtf(sred[0]+sred[1]+sred[2]+sred[3]);
    float sc = (nrm > 1.0f) ? 1.0f/(nrm + 1e-7f) : 1.0f;
    __nv_bfloat162 p0 = __floats2bfloat162_rn(ev.x*sc, ev.y*sc);
    __nv_bfloat162 p1 = __floats2bfloat162_rn(ev.z*sc, ev.w*sc);
    __nv_bfloat162* op = (__nv_bfloat162*)(g_X0b + (size_t)r*512);
    op[tid*2]   = p0;
    op[tid*2+1] = p1;
}

// ---------------- weight fp32 -> bf16 conversion ----------------
__global__ void convert_weights(const float* __restrict__ wi0, const float* __restrict__ wh0,
                                const float* __restrict__ wi1, const float* __restrict__ wh1)
{
    const int N0 = 2*2048*512;
    const int N1 = 2*2048*512;
    const int N2 = 2*2048*1024;
    const int N3 = 2*2048*512;
    int total = N0+N1+N2+N3;
    for (int i = blockIdx.x*blockDim.x + threadIdx.x; i < total; i += gridDim.x*blockDim.x) {
        if (i < N0)                    g_WI0b[i] = __float2bfloat16(wi0[i]);
        else if (i < N0+N1)            g_WH0b[i-N0] = __float2bfloat16(wh0[i-N0]);
        else if (i < N0+N1+N2)         g_WI1b[i-N0-N1] = __float2bfloat16(wi1[i-N0-N1]);
        else                           g_WH1b[i-N0-N1-N2] = __float2bfloat16(wh1[i-N0-N1-N2]);
    }
}

// ---------------- bf16 tensor-core input-projection GEMM (proven) ----------------
__global__ __launch_bounds__(256) void gemm_pre_mma(int layer, const float* __restrict__ bias)
{
    const bf16* A0 = layer ? g_HA0 : g_X0b;
    const bf16* A1 = layer ? g_HA1 : g_X0b;
    const bf16* W  = layer ? g_WI1b : g_WI0b;
    const int K  = layer ? 1024 : 512;
    const int m0 = blockIdx.y << 7;
    const int n0 = blockIdx.x << 7;

    extern __shared__ char smraw[];
    bf16* As = (bf16*)smraw;            // 2 stages x [128][64]
    bf16* Bs = As + 2*128*64;
    unsigned AsB = su32(As), BsB = su32(Bs);

    const int tid = threadIdx.x;
    const int warp = tid>>5, lane = tid&31;
    const int wm = warp>>2, wn = warp&3;

    float acc[4][4][4];
    #pragma unroll
    for (int i=0;i<4;i++)
        #pragma unroll
        for (int j=0;j<4;j++)
            #pragma unroll
            for (int k=0;k<4;k++) acc[i][j][k]=0.f;

    const int srow = tid>>1;
    const int skc0 = (tid&1)*4;
    const size_t arow = (size_t)(m0+srow)*512;
    const bf16* Wg = W + (size_t)(n0+srow)*K + skc0*8;
    unsigned AsRow = AsB + srow*128;
    unsigned BsRow = BsB + srow*128;

    const int iters = K >> 6;
    #pragma unroll
    for (int i=0;i<4;i++){
        int kc = skc0+i;
        unsigned sw = ((kc ^ (srow&7))<<4);
        cp16(AsRow + sw, A0 + arow + skc0*8 + i*8);
        cp16(BsRow + sw, Wg + i*8);
    }
    cpcommit();

    for (int kt=0; kt<iters; kt++){
        int s = kt&1;
        if (kt+1 < iters){
            int koff = (kt+1)<<6;
            const bf16* Asrc = (koff < 512) ? (A0 + arow + koff) : (A1 + arow + koff - 512);
            #pragma unroll
            for (int i=0;i<4;i++){
                int kc = skc0+i;
                unsigned sw = ((s^1)*128*128) + ((kc ^ (srow&7))<<4);
                cp16(AsRow + sw, Asrc + skc0*8 + i*8);
                cp16(BsRow + sw, Wg + koff + i*8);
            }
            cpcommit();
            cpwait<1>();
        } else {
            cpwait<0>();
        }
        __syncthreads();

        unsigned Ab = AsB + s*128*128;
        unsigned Bb = BsB + s*128*128;
        #pragma unroll
        for (int kk=0; kk<4; kk++){
            unsigned af[4][4];
            #pragma unroll
            for (int mt=0; mt<4; mt++){
                int row = wm*64 + mt*16 + (lane&15);
                int ch  = kk*2 + (lane>>4);
                ldsm4(af[mt][0],af[mt][1],af[mt][2],af[mt][3],
                      Ab + row*128 + ((ch ^ (row&7))<<4));
            }
            unsigned bfr[2][4];
            #pragma unroll
            for (int np=0; np<2; np++){
                int row = wn*32 + np*16 + (lane&7) + ((lane>=16)?8:0);
                int ch  = kk*2 + ((lane>>3)&1);
                ldsm4(bfr[np][0],bfr[np][1],bfr[np][2],bfr[np][3],
                      Bb + row*128 + ((ch ^ (row&7))<<4));
            }
            #pragma unroll
            for (int mt=0; mt<4; mt++)
                #pragma unroll
                for (int nt=0; nt<4; nt++)
                    mma16816(acc[mt][nt], af[mt], bfr[nt>>1][(nt&1)*2], bfr[nt>>1][(nt&1)*2+1]);
        }
        __syncthreads();
    }

    const int r = lane>>2, cp2 = (lane&3)*2;
    #pragma unroll
    for (int mt=0; mt<4; mt++){
        #pragma unroll
        for (int nt=0; nt<4; nt++){
            int m = m0 + wm*64 + mt*16 + r;
            int n = n0 + wn*32 + nt*8 + cp2;
            int dir  = n >> 11;
            int c2   = n & 2047;
            int gate = c2 >> 9;
            int j    = c2 & 511;
            int jb   = j >> 3;
            int jj   = j & 7;
            float2 bv = *(const float2*)(bias + n);
            float2 o0 = make_float2(acc[mt][nt][0]+bv.x, acc[mt][nt][1]+bv.y);
            float2 o1 = make_float2(acc[mt][nt][2]+bv.x, acc[mt][nt][3]+bv.y);
            size_t base = (((size_t)(dir*64 + jb)*MM) + m)*32 + gate*8 + jj;
            *(float2*)&g_PRE[base]        = o0;
            *(float2*)&g_PRE[base + 8*32] = o1;   // row m+8
        }
    }
}

// ---------------- persistent LSTM scan: batch-half phased pipeline ----------------
// 128 blocks (1/SM), 8 j/block, 256 threads. Per step:
//  phase A: [warps4-7: poll B1(s-1) flags, stage B1 h]  mma B0 | gates B0 | signal B0(s)
//  phase B: [warps0-3: poll B0(s) flags, stage B0 h]    mma B1 | gates B1 | signal B1(s)
// Sync+stage of each half hides under compute of the other half.
__global__ __launch_bounds__(256, 1) void lstm_scan_mma(int layer)
{
    extern __shared__ char smraw[];
    bf16*  Ws   = (bf16*)smraw;                              // 32768 B
    char*  Asm  = smraw + 32*1024;                           // 128 x 1040 = 133120 B
    float* zb   = (float*)(smraw + 32*1024 + 133120);        // [64][40] 10240 B
    float* sPre = (float*)(smraw + 32*1024 + 133120 + 10240);// [128][32] 16384 B
    __shared__ __align__(8) unsigned long long mbars[3];     // A0, A1, PRE

    bf16* Hbuf = layer ? (blockIdx.x >= 64 ? g_HB1 : g_HB0)
                       : (blockIdx.x >= 64 ? g_HA1 : g_HA0);
    const bf16* WH = layer ? g_WH1b : g_WH0b;
    const int bid = blockIdx.x;
    const int dir = bid >> 6;
    const int blk = bid & 63;
    const int j0  = blk << 3;
    const int tid = threadIdx.x;
    const int warp = tid>>5, lane = tid&31;
    const int wm = warp>>2;            // 0..1 : 32 batch rows each (within half)
    const int wn = warp&3;             // 0..3 : 8 N cols each (= gate wn)
    unsigned WsB = su32(Ws), AsB = su32(Asm), sPreB = su32(sPre);
    unsigned mbA0 = su32(&mbars[0]), mbA1 = su32(&mbars[1]), mbP = su32(&mbars[2]);

    if (tid == 0){
        mbar_init(mbA0, 1);
        mbar_init(mbA1, 1);
        mbar_init(mbP, 1);
        asm volatile("fence.proxy.async.shared::cta;" ::: "memory");
    }
    // ---- load Whh slice (32 rows x 512) once, swizzled ----
    {
        const bf16* wb = WH + (size_t)dir*2048*512;
        int rr = tid>>3;
        int kc0 = (tid&7)*8;
        int wrow = ((rr>>3)<<9) + j0 + (rr&7);
        const bf16* gp = wb + (size_t)wrow*512 + kc0*8;
        unsigned srw = WsB + rr*1024;
        #pragma unroll
        for (int i=0;i<8;i++){
            int kc = kc0+i;
            cp16(srw + ((kc ^ (rr&7))<<4), gp + i*8);
        }
        cpcommit(); cpwait<0>();
    }
    __syncthreads();

    // gates map: thread -> (local b = tid>>2, 2 j's at (tid&3)*2)
    const int gbl  = tid>>2;           // 0..63
    const int jsel = (tid&3)*2;        // 0,2,4,6
    float creg0[2] = {0.f, 0.f};
    float creg1[2] = {0.f, 0.f};

    unsigned* flagRow0 = &g_flags[layer][dir][0][0][0];   // stride per step = 2*64*32

    for (int s=0; s<TT; s++){
        const int t_out = dir ? (TT-1-s) : s;

        // ---- PRE: one 16KB bulk copy for the full batch at step start ----
        if (tid == 0){
            const float* prer = g_PRE + (((size_t)(dir*64 + blk)*MM) + (size_t)t_out*BB)*32;
            mbar_expect(mbP, 16384u);
            bulkcp(sPreB, prer, 16384u, mbP);
        }

        // ============ PHASE A : batch rows 0..63 ============
        float acc0[4] = {0.f,0.f,0.f,0.f};
        float acc1[4] = {0.f,0.f,0.f,0.f};

        if (s > 0){
            const int t_prev = dir ? (t_out+1) : (s-1);
            // warps 4..7: poll B1(s-1) flags (signaled a full phase ago), stage B1 rows
            if (tid >= 128){
                if (tid < 192){
                    const unsigned* fp = &g_flags[layer][dir][s-1][1][(tid-128)*32];
                    while (load_acq(fp) == 0u) { }
                }
                if (tid == 128) mbar_expect(mbA1, 65536u);
                bar_named(2, 128);
                int idx = tid - 128;               // 0..127
                int row = 64 + (idx>>1);
                bulkcp(AsB + row*1040 + (idx&1)*512,
                       Hbuf + ((size_t)t_prev*BB + row)*512 + (idx&1)*256, 512u, mbA1);
            }
            mbar_wait(mbA0, (unsigned)((s-1)&1));

            // MMA batch half 0 (rows 0..63)
            #pragma unroll 4
            for (int kk=0; kk<32; kk++){
                unsigned af0[4], af1[4], b0, b1;
                { int row = wm*32 + (lane&15);      int ch = kk*2 + (lane>>4);
                  ldsm4(af0[0],af0[1],af0[2],af0[3], AsB + row*1040 + ch*16); }
                { int row = wm*32 + 16 + (lane&15); int ch = kk*2 + (lane>>4);
                  ldsm4(af1[0],af1[1],af1[2],af1[3], AsB + row*1040 + ch*16); }
                { int row = wn*8 + (lane&7);        int ch = kk*2 + ((lane>>3)&1);
                  ldsm2(b0, b1, WsB + row*1024 + ((ch ^ (row&7))<<4)); }
                mma16816(acc0, af0, b0, b1);
                mma16816(acc1, af1, b0, b1);
            }
        }
        __syncthreads();
        {   // zb exchange half0
            int r = lane>>2, cq = (lane&3)*2;
            int mr = wm*32 + r, nc = wn*8 + cq;
            zb[mr*40 + nc]        = acc0[0]; zb[mr*40 + nc + 1]        = acc0[1];
            zb[(mr+8)*40 + nc]    = acc0[2]; zb[(mr+8)*40 + nc + 1]    = acc0[3];
            zb[(mr+16)*40 + nc]   = acc1[0]; zb[(mr+16)*40 + nc + 1]   = acc1[1];
            zb[(mr+24)*40 + nc]   = acc1[2]; zb[(mr+24)*40 + nc + 1]   = acc1[3];
        }
        mbar_wait(mbP, (unsigned)(s&1));
        __syncthreads();
        {   // gates half0
            const float* zr = zb + gbl*40;
            const float* sp = sPre + gbl*32;
            float2 zi = *(const float2*)(zr + jsel);
            float2 zf = *(const float2*)(zr + 8 + jsel);
            float2 zg = *(const float2*)(zr + 16 + jsel);
            float2 zo = *(const float2*)(zr + 24 + jsel);
            float2 pi = *(const float2*)(sp + jsel);
            float2 pf = *(const float2*)(sp + 8 + jsel);
            float2 pg = *(const float2*)(sp + 16 + jsel);
            float2 po = *(const float2*)(sp + 24 + jsel);
            creg0[0] = fsig(zf.x+pf.x)*creg0[0] + fsig(zi.x+pi.x)*ftanh(zg.x+pg.x);
            creg0[1] = fsig(zf.y+pf.y)*creg0[1] + fsig(zi.y+pi.y)*ftanh(zg.y+pg.y);
            float h0 = fsig(zo.x+po.x)*ftanh(creg0[0]);
            float h1 = fsig(zo.y+po.y)*ftanh(creg0[1]);
            __nv_bfloat162 hp = __floats2bfloat162_rn(h0, h1);
            *(unsigned*)&Hbuf[((size_t)t_out*BB + gbl)*512 + j0 + jsel] = *(unsigned*)&hp;
        }
        __syncthreads();
        if (tid == 0) st_release(&g_flags[layer][dir][s][0][blk*32], 1u);

        // ============ PHASE B : batch rows 64..127 ============
        #pragma unroll
        for (int k=0;k<4;k++){ acc0[k]=0.f; acc1[k]=0.f; }

        // warps 0..3: poll B0(s) flags (just signaled; skew-only wait), stage B0 rows for step s+1
        if (tid < 128 && s < TT-1){
            if (tid < 64){
                const unsigned* fp = &g_flags[layer][dir][s][0][tid*32];
                while (load_acq(fp) == 0u) { }
            }
            if (tid == 0) mbar_expect(mbA0, 65536u);
            bar_named(1, 128);
            int row = tid>>1;                       // 0..63
            bulkcp(AsB + row*1040 + (tid&1)*512,
                   Hbuf + ((size_t)t_out*BB + row)*512 + (tid&1)*256, 512u, mbA0);
        }

        if (s > 0){
            mbar_wait(mbA1, (unsigned)((s-1)&1));

            // MMA batch half 1 (rows 64..127)
            #pragma unroll 4
            for (int kk=0; kk<32; kk++){
                unsigned af0[4], af1[4], b0, b1;
                { int row = 64 + wm*32 + (lane&15);      int ch = kk*2 + (lane>>4);
                  ldsm4(af0[0],af0[1],af0[2],af0[3], AsB + row*1040 + ch*16); }
                { int row = 64 + wm*32 + 16 + (lane&15); int ch = kk*2 + (lane>>4);
                  ldsm4(af1[0],af1[1],af1[2],af1[3], AsB + row*1040 + ch*16); }
                { int row = wn*8 + (lane&7);             int ch = kk*2 + ((lane>>3)&1);
                  ldsm2(b0, b1, WsB + row*1024 + ((ch ^ (row&7))<<4)); }
                mma16816(acc0, af0, b0, b1);
                mma16816(acc1, af1, b0, b1);
            }
        }
        __syncthreads();
        {   // zb exchange half1
            int r = lane>>2, cq = (lane&3)*2;
            int mr = wm*32 + r, nc = wn*8 + cq;
            zb[mr*40 + nc]        = acc0[0]; zb[mr*40 + nc + 1]        = acc0[1];
            zb[(mr+8)*40 + nc]    = acc0[2]; zb[(mr+8)*40 + nc + 1]    = acc0[3];
            zb[(mr+16)*40 + nc]   = acc1[0]; zb[(mr+16)*40 + nc + 1]   = acc1[1];
            zb[(mr+24)*40 + nc]   = acc1[2]; zb[(mr+24)*40 + nc + 1]   = acc1[3];
        }
        __syncthreads();
        {   // gates half1
            int bg = 64 + gbl;
            const float* zr = zb + gbl*40;
            const float* sp = sPre + bg*32;
            float2 zi = *(const float2*)(zr + jsel);
            float2 zf = *(const float2*)(zr + 8 + jsel);
            float2 zg = *(const float2*)(zr + 16 + jsel);
            float2 zo = *(const float2*)(zr + 24 + jsel);
            float2 pi = *(const float2*)(sp + jsel);
            float2 pf = *(const float2*)(sp + 8 + jsel);
            float2 pg = *(const float2*)(sp + 16 + jsel);
            float2 po = *(const float2*)(sp + 24 + jsel);
            creg1[0] = fsig(zf.x+pf.x)*creg1[0] + fsig(zi.x+pi.x)*ftanh(zg.x+pg.x);
            creg1[1] = fsig(zf.y+pf.y)*creg1[1] + fsig(zi.y+pi.y)*ftanh(zg.y+pg.y);
            float h0 = fsig(zo.x+po.x)*ftanh(creg1[0]);
            float h1 = fsig(zo.y+po.y)*ftanh(creg1[1]);
            __nv_bfloat162 hp = __floats2bfloat162_rn(h0, h1);
            *(unsigned*)&Hbuf[((size_t)t_out*BB + bg)*512 + j0 + jsel] = *(unsigned*)&hp;
        }
        __syncthreads();
        if (tid == 0) st_release(&g_flags[layer][dir][s][1][blk*32], 1u);
    }
    (void)flagRow0;
}

// ---------------- classifier emissions (h in split bf16 buffers) ----------------
__global__ void emissions_kernel(const float* __restrict__ clsW, const float* __restrict__ clsB)
{
    int warp = threadIdx.x >> 5, lane = threadIdx.x & 31;
    int row = (blockIdx.x << 3) + warp;
    const __nv_bfloat162* h20 = (const __nv_bfloat162*)(g_HB0 + (size_t)row * 512);
    const __nv_bfloat162* h21 = (const __nv_bfloat162*)(g_HB1 + (size_t)row * 512);
    float2 hv[16];
    #pragma unroll
    for (int m=0;m<8;m++)  hv[m]   = __bfloat1622float2(h20[lane + (m<<5)]);
    #pragma unroll
    for (int m=0;m<8;m++)  hv[m+8] = __bfloat1622float2(h21[lane + (m<<5)]);
    #pragma unroll
    for (int c=0;c<CC;c++) {
        const float2* w2 = (const float2*)(clsW + c*1024);
        float s = 0.f;
        #pragma unroll
        for (int m=0;m<16;m++){
            float2 wv = w2[lane + (m<<5)];
            s += hv[m].x*wv.x + hv[m].y*wv.y;
        }
        #pragma unroll
        for (int o=16;o;o>>=1) s += __shfl_xor_sync(0xffffffffu, s, o);
        if (lane==0) g_EM[(size_t)row*CC + c] = s + clsB[c];
    }
}

// ---------------- fused CRF (numerator + denominator), one warp per batch ----------------
__global__ void crf_kernel(const int* __restrict__ y, const float* __restrict__ trans,
                           const float* __restrict__ cstart, const float* __restrict__ cend)
{
    __shared__ float st[CC*CC];
    if (threadIdx.x < CC*CC) st[threadIdx.x] = trans[threadIdx.x];
    __syncthreads();

    int b = (blockIdx.x << 3) + (threadIdx.x >> 5);
    int lane = threadIdx.x & 31;
    int c = lane < CC ? lane : CC-1;
    float tcol[CC];
    #pragma unroll
    for (int i=0;i<CC;i++) tcol[i] = st[i*CC + c];

    int y0 = y[b*TT];
    int prev = y0 > 0 ? y0 : 0;
    float alpha = cstart[c] + g_EM[(size_t)b*CC + c];
    float sc = __shfl_sync(0xffffffffu, alpha, prev);
    int cnt = (y0 > -1) ? 1 : 0;

    float e_next = g_EM[((size_t)1*BB + b)*CC + c];
    int   y_next = y[b*TT + 1];

    for (int t=1;t<TT;t++) {
        float e  = e_next;
        int   yt = y_next;
        if (t+1 < TT){
            e_next = g_EM[((size_t)(t+1)*BB + b)*CC + c];
            y_next = y[b*TT + t + 1];
        }
        float av[CC]; float mx = -1e30f;
        #pragma unroll
        for (int i=0;i<CC;i++) { av[i] = __shfl_sync(0xffffffffu, alpha, i) + tcol[i]; mx = fmaxf(mx, av[i]); }
        float su = 0.f;
        #pragma unroll
        for (int i=0;i<CC;i++) su += expf(av[i]-mx);
        float nxt = mx + logf(su) + e;
        bool m = (yt > -1);
        if (m) alpha = nxt;
        int tgt = yt > 0 ? yt : 0;
        float etg = __shfl_sync(0xffffffffu, e, tgt);
        sc += (st[prev*CC + tgt] + etg) * (m ? 1.f : 0.f);
        prev = tgt;
        cnt += m ? 1 : 0;
    }
    int se = cnt - 1; if (se < 0) se = 0;
    int yl = y[b*TT + se];
    int lt = yl > 0 ? yl : 0;
    sc += cend[lt];

    float v = alpha + cend[c];
    float mx = -1e30f;
    #pragma unroll
    for (int i=0;i<CC;i++) mx = fmaxf(mx, __shfl_sync(0xffffffffu, v, i));
    float su = 0.f;
    #pragma unroll
    for (int i=0;i<CC;i++) su += expf(__shfl_sync(0xffffffffu, v, i) - mx);
    if (lane==0) g_LLH[b] = sc - (mx + logf(su));
}

// ---------------- final reduction ----------------
__global__ void final_kernel(float* __restrict__ out)
{
    int tid = threadIdx.x;
    float v = g_LLH[tid];
    #pragma unroll
    for (int o=16;o;o>>=1) v += __shfl_xor_sync(0xffffffffu, v, o);
    __shared__ float sr[4];
    if ((tid&31)==0) sr[tid>>5] = v;
    __syncthreads();
    if (tid==0) out[0] = -(sr[0]+sr[1]+sr[2]+sr[3]) / 128.0f;
}

// ---------------- launch ----------------
extern "C" void kernel_launch(void* const* d_in, const int* in_sizes, int n_in,
                              void* d_out, int out_size)
{
    const int*   x        = (const int*)  d_in[0];
    const int*   y        = (const int*)  d_in[1];
    const float* embed    = (const float*)d_in[2];
    const float* w_ih_l0  = (const float*)d_in[3];
    const float* w_hh_l0  = (const float*)d_in[4];
    const float* b_l0     = (const float*)d_in[5];
    const float* w_ih_l1  = (const float*)d_in[6];
    const float* w_hh_l1  = (const float*)d_in[7];
    const float* b_l1     = (const float*)d_in[8];
    const float* cls_w    = (const float*)d_in[9];
    const float* cls_b    = (const float*)d_in[10];
    const float* crf_start= (const float*)d_in[11];
    const float* crf_end  = (const float*)d_in[12];
    const float* crf_trans= (const float*)d_in[13];
    float* out = (float*)d_out;

    const int GEMM_SMEM = 2*(128*64)*2*2;                           // 65536 B
    const int SCAN_SMEM = 32*1024 + 133120 + 10240 + 16384;         // 192512 B
    cudaFuncSetAttribute(gemm_pre_mma, cudaFuncAttributeMaxDynamicSharedMemorySize, GEMM_SMEM);
    cudaFuncSetAttribute(lstm_scan_mma, cudaFuncAttributeMaxDynamicSharedMemorySize, SCAN_SMEM);

    reset_flags<<<2048, 64>>>();
    embed_kernel<<<MM, 128>>>(x, embed);
    convert_weights<<<512, 256>>>(w_ih_l0, w_hh_l0, w_ih_l1, w_hh_l1);

    gemm_pre_mma<<<dim3(32,256), 256, GEMM_SMEM>>>(0, b_l0);
    lstm_scan_mma<<<128, 256, SCAN_SMEM>>>(0);
    gemm_pre_mma<<<dim3(32,256), 256, GEMM_SMEM>>>(1, b_l1);
    lstm_scan_mma<<<128, 256, SCAN_SMEM>>>(1);

    emissions_kernel<<<4096, 256>>>(cls_w, cls_b);
    crf_kernel<<<16, 256>>>(y, crf_trans, crf_start, crf_end);
    final_kernel<<<1, 128>>>(out);
}

// round 12
// speedup vs baseline: 1.2254x; 1.2254x over previous
#include <cuda_runtime.h>
#include <cuda_bf16.h>
#include <math.h>

#define TT 256
#define BB 128
#define CC 9
#define MM (TT*BB)      // 32768 rows

typedef __nv_bfloat16 bf16;

// ---------------- scratch (static device globals; no allocs) ----------------
__device__ bf16  g_X0b[(size_t)MM*512];       // layer0 input, bf16 (T,B,512)
__device__ bf16  g_HA0[(size_t)MM*512];       // layer0 h fwd (T,B,512)
__device__ bf16  g_HA1[(size_t)MM*512];       // layer0 h bwd
__device__ bf16  g_HB0[(size_t)MM*512];       // layer1 h fwd
__device__ bf16  g_HB1[(size_t)MM*512];       // layer1 h bwd
// PRE scan-major: [dir][jb(64)][t*B][32]  (gate*8 + jj within 32)
__device__ float g_PRE[(size_t)2*64*MM*32];
__device__ bf16  g_WI0b[4096*512];            // w_ih_l0 bf16
__device__ bf16  g_WI1b[(size_t)4096*1024];   // w_ih_l1 bf16
__device__ bf16  g_WH0b[2*2048*512];          // w_hh_l0 bf16
__device__ bf16  g_WH1b[2*2048*512];          // w_hh_l1 bf16
__device__ float g_EM[(size_t)MM*CC];
__device__ float g_LLH[BB];
// per-block done flags: [layer][dir][step][block*32] (128B apart)
__device__ unsigned g_flags[2][2][TT][64*32];

__device__ __forceinline__ float fsig(float x){ return 1.0f/(1.0f+__expf(-x)); }
__device__ __forceinline__ float ftanh(float x){
    float ax = fabsf(x);
    float t = __expf(-2.0f*ax);
    float r = (1.0f - t)/(1.0f + t);
    return copysignf(r, x);
}

// ---------------- PTX helpers ----------------
__device__ __forceinline__ unsigned su32(const void* p){ return (unsigned)__cvta_generic_to_shared(p); }
__device__ __forceinline__ void cp16(unsigned s, const void* g){
    asm volatile("cp.async.cg.shared.global [%0], [%1], 16;\n" :: "r"(s), "l"(g));
}
__device__ __forceinline__ void cpcommit(){ asm volatile("cp.async.commit_group;\n"); }
template<int N> __device__ __forceinline__ void cpwait(){ asm volatile("cp.async.wait_group %0;\n"::"n"(N)); }
__device__ __forceinline__ void ldsm4(unsigned &r0, unsigned &r1, unsigned &r2, unsigned &r3, unsigned addr){
    asm volatile("ldmatrix.sync.aligned.m8n8.x4.shared.b16 {%0,%1,%2,%3}, [%4];\n"
        : "=r"(r0),"=r"(r1),"=r"(r2),"=r"(r3) : "r"(addr));
}
__device__ __forceinline__ void mma16816(float* c, const unsigned* a, unsigned b0, unsigned b1){
    asm volatile("mma.sync.aligned.m16n8k16.row.col.f32.bf16.bf16.f32 "
        "{%0,%1,%2,%3}, {%4,%5,%6,%7}, {%8,%9}, {%0,%1,%2,%3};\n"
        : "+f"(c[0]),"+f"(c[1]),"+f"(c[2]),"+f"(c[3])
        : "r"(a[0]),"r"(a[1]),"r"(a[2]),"r"(a[3]),"r"(b0),"r"(b1));
}
__device__ __forceinline__ void st_release(unsigned* p, unsigned v){
    asm volatile("st.release.gpu.global.u32 [%0], %1;" :: "l"(p), "r"(v) : "memory");
}
__device__ __forceinline__ unsigned load_acq(const unsigned* p){
    unsigned v;
    asm volatile("ld.acquire.gpu.global.u32 %0, [%1];" : "=r"(v) : "l"(p) : "memory");
    return v;
}
__device__ __forceinline__ void mbar_init(unsigned m, unsigned cnt){
    asm volatile("mbarrier.init.shared.b64 [%0], %1;" :: "r"(m), "r"(cnt) : "memory");
}
__device__ __forceinline__ void mbar_expect(unsigned m, unsigned bytes){
    asm volatile("mbarrier.arrive.expect_tx.shared.b64 _, [%0], %1;" :: "r"(m), "r"(bytes) : "memory");
}
__device__ __forceinline__ void bulkcp(unsigned dst, const void* src, unsigned bytes, unsigned m){
    asm volatile("cp.async.bulk.shared::cta.global.mbarrier::complete_tx::bytes [%0], [%1], %2, [%3];"
        :: "r"(dst), "l"(src), "r"(bytes), "r"(m) : "memory");
}
__device__ __forceinline__ void mbar_wait(unsigned m, unsigned parity){
    asm volatile(
        "{\n\t.reg .pred P;\n\t"
        "WL%=:\n\t"
        "mbarrier.try_wait.parity.acquire.cta.shared::cta.b64 P, [%0], %1, 0x989680;\n\t"
        "@P bra WD%=;\n\t"
        "bra WL%=;\n\t"
        "WD%=:\n\t}"
        :: "r"(m), "r"(parity) : "memory");
}
__device__ __forceinline__ void bar_named(int id, int nthreads){
    asm volatile("bar.sync %0, %1;" :: "r"(id), "r"(nthreads) : "memory");
}

// ---------------- reset flags (once per launch; graph-replay safe) ----------------
__global__ void reset_flags(){
    int l = blockIdx.x >> 9;
    int d = (blockIdx.x >> 8) & 1;
    int s = blockIdx.x & 255;
    g_flags[l][d][s][threadIdx.x*32] = 0u;
}

// ---------------- embedding lookup + norm clip -> bf16 ----------------
__global__ void embed_kernel(const int* __restrict__ x, const float* __restrict__ embed)
{
    int r = blockIdx.x;            // r = t*BB + b
    int t = r >> 7;
    int b = r & 127;
    int v = x[b*TT + t];
    const float* e = embed + (size_t)v * 512;
    int tid = threadIdx.x;         // 128
    float4 ev = ((const float4*)e)[tid];
    float ss = ev.x*ev.x + ev.y*ev.y + ev.z*ev.z + ev.w*ev.w;
    #pragma unroll
    for (int o = 16; o; o >>= 1) ss += __shfl_xor_sync(0xffffffffu, ss, o);
    __shared__ float sred[4];
    if ((tid & 31) == 0) sred[tid>>5] = ss;
    __syncthreads();
    float nrm = sqrtf(sred[0]+sred[1]+sred[2]+sred[3]);
    float sc = (nrm > 1.0f) ? 1.0f/(nrm + 1e-7f) : 1.0f;
    __nv_bfloat162 p0 = __floats2bfloat162_rn(ev.x*sc, ev.y*sc);
    __nv_bfloat162 p1 = __floats2bfloat162_rn(ev.z*sc, ev.w*sc);
    __nv_bfloat162* op = (__nv_bfloat162*)(g_X0b + (size_t)r*512);
    op[tid*2]   = p0;
    op[tid*2+1] = p1;
}

// ---------------- weight fp32 -> bf16 conversion (vectorized, 8 elems/thread) ----------------
__device__ __forceinline__ void conv8(bf16* dst, const float* src, size_t i8){
    const float4* s4 = (const float4*)(src + i8*8);
    float4 a = s4[0], b = s4[1];
    __nv_bfloat162 q0 = __floats2bfloat162_rn(a.x, a.y);
    __nv_bfloat162 q1 = __floats2bfloat162_rn(a.z, a.w);
    __nv_bfloat162 q2 = __floats2bfloat162_rn(b.x, b.y);
    __nv_bfloat162 q3 = __floats2bfloat162_rn(b.z, b.w);
    uint4 o; o.x = *(unsigned*)&q0; o.y = *(unsigned*)&q1; o.z = *(unsigned*)&q2; o.w = *(unsigned*)&q3;
    *(uint4*)(dst + i8*8) = o;
}
__global__ void convert_weights(const float* __restrict__ wi0, const float* __restrict__ wh0,
                                const float* __restrict__ wi1, const float* __restrict__ wh1)
{
    const size_t N0 = 2u*2048*512/8;      // chunks of 8
    const size_t N1 = 2u*2048*512/8;
    const size_t N2 = 2u*2048*1024/8;
    const size_t N3 = 2u*2048*512/8;
    size_t total = N0+N1+N2+N3;
    size_t stride = (size_t)gridDim.x*blockDim.x;
    for (size_t i = (size_t)blockIdx.x*blockDim.x + threadIdx.x; i < total; i += stride) {
        if (i < N0)                 conv8(g_WI0b, wi0, i);
        else if (i < N0+N1)         conv8(g_WH0b, wh0, i-N0);
        else if (i < N0+N1+N2)      conv8(g_WI1b, wi1, i-N0-N1);
        else                        conv8(g_WH1b, wh1, i-N0-N1-N2);
    }
}

// ---------------- bf16 tensor-core input-projection GEMM (2 blocks/SM) ----------------
__global__ __launch_bounds__(256, 2) void gemm_pre_mma(int layer, const float* __restrict__ bias)
{
    const bf16* A0 = layer ? g_HA0 : g_X0b;
    const bf16* A1 = layer ? g_HA1 : g_X0b;
    const bf16* W  = layer ? g_WI1b : g_WI0b;
    const int K  = layer ? 1024 : 512;
    const int m0 = blockIdx.y << 7;
    const int n0 = blockIdx.x << 7;

    extern __shared__ char smraw[];
    bf16* As = (bf16*)smraw;            // 2 stages x [128][64]
    bf16* Bs = As + 2*128*64;
    unsigned AsB = su32(As), BsB = su32(Bs);

    const int tid = threadIdx.x;
    const int warp = tid>>5, lane = tid&31;
    const int wm = warp>>2, wn = warp&3;

    float acc[4][4][4];
    #pragma unroll
    for (int i=0;i<4;i++)
        #pragma unroll
        for (int j=0;j<4;j++)
            #pragma unroll
            for (int k=0;k<4;k++) acc[i][j][k]=0.f;

    const int srow = tid>>1;
    const int skc0 = (tid&1)*4;
    const size_t arow = (size_t)(m0+srow)*512;
    const bf16* Wg = W + (size_t)(n0+srow)*K + skc0*8;
    unsigned AsRow = AsB + srow*128;
    unsigned BsRow = BsB + srow*128;

    const int iters = K >> 6;
    #pragma unroll
    for (int i=0;i<4;i++){
        int kc = skc0+i;
        unsigned sw = ((kc ^ (srow&7))<<4);
        cp16(AsRow + sw, A0 + arow + skc0*8 + i*8);
        cp16(BsRow + sw, Wg + i*8);
    }
    cpcommit();

    for (int kt=0; kt<iters; kt++){
        int s = kt&1;
        if (kt+1 < iters){
            int koff = (kt+1)<<6;
            const bf16* Asrc = (koff < 512) ? (A0 + arow + koff) : (A1 + arow + koff - 512);
            #pragma unroll
            for (int i=0;i<4;i++){
                int kc = skc0+i;
                unsigned sw = ((s^1)*128*128) + ((kc ^ (srow&7))<<4);
                cp16(AsRow + sw, Asrc + skc0*8 + i*8);
                cp16(BsRow + sw, Wg + koff + i*8);
            }
            cpcommit();
            cpwait<1>();
        } else {
            cpwait<0>();
        }
        __syncthreads();

        unsigned Ab = AsB + s*128*128;
        unsigned Bb = BsB + s*128*128;
        #pragma unroll
        for (int kk=0; kk<4; kk++){
            unsigned af[4][4];
            #pragma unroll
            for (int mt=0; mt<4; mt++){
                int row = wm*64 + mt*16 + (lane&15);
                int ch  = kk*2 + (lane>>4);
                ldsm4(af[mt][0],af[mt][1],af[mt][2],af[mt][3],
                      Ab + row*128 + ((ch ^ (row&7))<<4));
            }
            unsigned bfr[2][4];
            #pragma unroll
            for (int np=0; np<2; np++){
                int row = wn*32 + np*16 + (lane&7) + ((lane>=16)?8:0);
                int ch  = kk*2 + ((lane>>3)&1);
                ldsm4(bfr[np][0],bfr[np][1],bfr[np][2],bfr[np][3],
                      Bb + row*128 + ((ch ^ (row&7))<<4));
            }
            #pragma unroll
            for (int mt=0; mt<4; mt++)
                #pragma unroll
                for (int nt=0; nt<4; nt++)
                    mma16816(acc[mt][nt], af[mt], bfr[nt>>1][(nt&1)*2], bfr[nt>>1][(nt&1)*2+1]);
        }
        __syncthreads();
    }

    const int r = lane>>2, cp2 = (lane&3)*2;
    #pragma unroll
    for (int mt=0; mt<4; mt++){
        #pragma unroll
        for (int nt=0; nt<4; nt++){
            int m = m0 + wm*64 + mt*16 + r;
            int n = n0 + wn*32 + nt*8 + cp2;
            int dir  = n >> 11;
            int c2   = n & 2047;
            int gate = c2 >> 9;
            int j    = c2 & 511;
            int jb   = j >> 3;
            int jj   = j & 7;
            float2 bv = *(const float2*)(bias + n);
            float2 o0 = make_float2(acc[mt][nt][0]+bv.x, acc[mt][nt][1]+bv.y);
            float2 o1 = make_float2(acc[mt][nt][2]+bv.x, acc[mt][nt][3]+bv.y);
            size_t base = (((size_t)(dir*64 + jb)*MM) + m)*32 + gate*8 + jj;
            *(float2*)&g_PRE[base]        = o0;
            *(float2*)&g_PRE[base + 8*32] = o1;   // row m+8
        }
    }
}

// ---------------- persistent LSTM scan: 128 blocks (1/SM), 8 j/block ----------------
// R10 proven structure (4737us): split wait with named barriers matching stager groups.
__global__ __launch_bounds__(256, 1) void lstm_scan_mma(int layer)
{
    extern __shared__ char smraw[];
    bf16*  Ws   = (bf16*)smraw;                              // 32768 B
    char*  Asm  = smraw + 32*1024;                           // 128 x 1040 = 133120 B
    float* zb   = (float*)(smraw + 32*1024 + 133120);        // [128][40] 20480 B
    float* sPre = (float*)(smraw + 32*1024 + 133120 + 20480);// [128][32] 16384 B
    __shared__ __align__(8) unsigned long long mbars[3];     // H1, H2, PRE

    bf16* Hbuf = layer ? (blockIdx.x >= 64 ? g_HB1 : g_HB0)
                       : (blockIdx.x >= 64 ? g_HA1 : g_HA0);
    const bf16* WH = layer ? g_WH1b : g_WH0b;
    const int bid = blockIdx.x;
    const int dir = bid >> 6;
    const int blk = bid & 63;
    const int j0  = blk << 3;
    const int tid = threadIdx.x;
    const int warp = tid>>5, lane = tid&31;
    const int wm = warp>>1, wn = warp&1;
    unsigned WsB = su32(Ws), AsB = su32(Asm), sPreB = su32(sPre);
    unsigned mbH1 = su32(&mbars[0]), mbH2 = su32(&mbars[1]), mbP = su32(&mbars[2]);

    if (tid == 0){
        mbar_init(mbH1, 1);
        mbar_init(mbH2, 1);
        mbar_init(mbP, 1);
        asm volatile("fence.proxy.async.shared::cta;" ::: "memory");
    }
    // ---- load Whh slice (32 rows x 512) once, swizzled ----
    {
        const bf16* wb = WH + (size_t)dir*2048*512;
        int rr = tid>>3;
        int kc0 = (tid&7)*8;
        int wrow = ((rr>>3)<<9) + j0 + (rr&7);
        const bf16* gp = wb + (size_t)wrow*512 + kc0*8;
        unsigned srw = WsB + rr*1024;
        #pragma unroll
        for (int i=0;i<8;i++){
            int kc = kc0+i;
            cp16(srw + ((kc ^ (rr&7))<<4), gp + i*8);
        }
        cpcommit(); cpwait<0>();
    }
    __syncthreads();

    // cell state in registers: thread owns (b = tid>>1, j = j0 + (tid&1)*4 .. +3)
    float creg[4] = {0.f, 0.f, 0.f, 0.f};
    const int gb  = tid>>1;
    const int gh4 = (tid&1)*4;

    for (int s=0; s<TT; s++){
        const int t_out = dir ? (TT-1-s) : s;

        // ---- PRE: one contiguous 16KB bulk copy, issued pre-wait ----
        if (tid == 0){
            const float* prer = g_PRE + (((size_t)(dir*64 + blk)*MM) + (size_t)t_out*BB)*32;
            mbar_expect(mbP, 16384u);
            bulkcp(sPreB, prer, 16384u, mbP);
        }

        float acc[2][2][4];
        #pragma unroll
        for (int i=0;i<2;i++)
            #pragma unroll
            for (int j=0;j<2;j++)
                #pragma unroll
                for (int k=0;k<4;k++) acc[i][j][k]=0.f;

        if (s > 0){
            const unsigned pH = (unsigned)((s-1)&1);
            const int t_prev = dir ? (t_out+1) : (s-1);
            const bf16* hbase = Hbuf + (size_t)(t_prev*BB)*512;

            if (tid < 128){
                // half1 group: threads 0..31 poll half1 producer flags
                if (tid < 32){
                    const unsigned* fp = &g_flags[layer][dir][s-1][tid*32];
                    while (load_acq(fp) == 0u) { }
                    if (tid == 0) mbar_expect(mbH1, 65536u);
                }
                bar_named(1, 128);
                // 128 threads each stage one 512B row of half1
                bulkcp(AsB + tid*1040, hbase + (size_t)tid*512, 512u, mbH1);
            } else {
                // half2 group: threads 128..159 poll half2 producer flags
                if (tid < 160){
                    const unsigned* fp = &g_flags[layer][dir][s-1][(32 + (tid-128))*32];
                    while (load_acq(fp) == 0u) { }
                    if (tid == 128) mbar_expect(mbH2, 65536u);
                }
                bar_named(2, 128);
                int rr = tid - 128;
                bulkcp(AsB + rr*1040 + 512, hbase + (size_t)rr*512 + 256, 512u, mbH2);
            }

            mbar_wait(mbH1, pH);

            // mma over K first half (chunks 0..31)
            #pragma unroll 4
            for (int kk=0; kk<16; kk++){
                unsigned af[2][4];
                #pragma unroll
                for (int mt=0; mt<2; mt++){
                    int row = wm*32 + mt*16 + (lane&15);
                    int ch  = kk*2 + (lane>>4);
                    ldsm4(af[mt][0],af[mt][1],af[mt][2],af[mt][3],
                          AsB + row*1040 + ch*16);
                }
                unsigned bfr[4];
                {
                    int row = wn*16 + (lane&7) + ((lane>=16)?8:0);
                    int ch  = kk*2 + ((lane>>3)&1);
                    ldsm4(bfr[0],bfr[1],bfr[2],bfr[3],
                          WsB + row*1024 + ((ch ^ (row&7))<<4));
                }
                #pragma unroll
                for (int mt=0; mt<2; mt++){
                    mma16816(acc[mt][0], af[mt], bfr[0], bfr[1]);
                    mma16816(acc[mt][1], af[mt], bfr[2], bfr[3]);
                }
            }

            mbar_wait(mbH2, pH);

            // mma over K second half (chunks 32..63)
            #pragma unroll 4
            for (int kk=16; kk<32; kk++){
                unsigned af[2][4];
                #pragma unroll
                for (int mt=0; mt<2; mt++){
                    int row = wm*32 + mt*16 + (lane&15);
                    int ch  = kk*2 + (lane>>4);
                    ldsm4(af[mt][0],af[mt][1],af[mt][2],af[mt][3],
                          AsB + row*1040 + ch*16);
                }
                unsigned bfr[4];
                {
                    int row = wn*16 + (lane&7) + ((lane>=16)?8:0);
                    int ch  = kk*2 + ((lane>>3)&1);
                    ldsm4(bfr[0],bfr[1],bfr[2],bfr[3],
                          WsB + row*1024 + ((ch ^ (row&7))<<4));
                }
                #pragma unroll
                for (int mt=0; mt<2; mt++){
                    mma16816(acc[mt][0], af[mt], bfr[0], bfr[1]);
                    mma16816(acc[mt][1], af[mt], bfr[2], bfr[3]);
                }
            }
        }
        __syncthreads();

        // ---- exchange z through smem (stride 40 floats) ----
        {
            const int r = lane>>2, cq = (lane&3)*2;
            #pragma unroll
            for (int mt=0; mt<2; mt++)
                #pragma unroll
                for (int nt=0; nt<2; nt++){
                    int mr = wm*32 + mt*16 + r;
                    int nc = wn*16 + nt*8 + cq;
                    zb[mr*40 + nc]       = acc[mt][nt][0];
                    zb[mr*40 + nc+1]     = acc[mt][nt][1];
                    zb[(mr+8)*40 + nc]   = acc[mt][nt][2];
                    zb[(mr+8)*40 + nc+1] = acc[mt][nt][3];
                }
        }
        mbar_wait(mbP, (unsigned)(s&1));
        __syncthreads();

        // ---- gates: thread -> (gb, 4 j's), c in registers ----
        {
            const float* zr = zb + gb*40;
            const float* sp = sPre + gb*32;
            float4 zi = *(const float4*)(zr + gh4);
            float4 zf = *(const float4*)(zr + 8 + gh4);
            float4 zg = *(const float4*)(zr + 16 + gh4);
            float4 zo = *(const float4*)(zr + 24 + gh4);
            float4 pi = *(const float4*)(sp + gh4);
            float4 pf = *(const float4*)(sp + 8 + gh4);
            float4 pg = *(const float4*)(sp + 16 + gh4);
            float4 po = *(const float4*)(sp + 24 + gh4);

            float ho[4];
            float zis[4]={zi.x+pi.x, zi.y+pi.y, zi.z+pi.z, zi.w+pi.w};
            float zfs[4]={zf.x+pf.x, zf.y+pf.y, zf.z+pf.z, zf.w+pf.w};
            float zgs[4]={zg.x+pg.x, zg.y+pg.y, zg.z+pg.z, zg.w+pg.w};
            float zos[4]={zo.x+po.x, zo.y+po.y, zo.z+po.z, zo.w+po.w};
            #pragma unroll
            for (int u=0;u<4;u++){
                float fi=fsig(zis[u]), ff=fsig(zfs[u]), fg=ftanh(zgs[u]), fo=fsig(zos[u]);
                creg[u] = ff*creg[u] + fi*fg;
                ho[u] = fo*ftanh(creg[u]);
            }
            __nv_bfloat162 p0 = __floats2bfloat162_rn(ho[0],ho[1]);
            __nv_bfloat162 p1 = __floats2bfloat162_rn(ho[2],ho[3]);
            uint2 uv; uv.x = *(unsigned*)&p0; uv.y = *(unsigned*)&p1;
            *(uint2*)&Hbuf[((size_t)t_out*BB + gb)*512 + j0 + gh4] = uv;
        }

        __syncthreads();
        if (tid==0) st_release(&g_flags[layer][dir][s][blk*32], 1u);
    }
}

// ---------------- classifier emissions (h in split bf16 buffers) ----------------
__global__ void emissions_kernel(const float* __restrict__ clsW, const float* __restrict__ clsB)
{
    int warp = threadIdx.x >> 5, lane = threadIdx.x & 31;
    int row = (blockIdx.x << 3) + warp;
    const __nv_bfloat162* h20 = (const __nv_bfloat162*)(g_HB0 + (size_t)row * 512);
    const __nv_bfloat162* h21 = (const __nv_bfloat162*)(g_HB1 + (size_t)row * 512);
    float2 hv[16];
    #pragma unroll
    for (int m=0;m<8;m++)  hv[m]   = __bfloat1622float2(h20[lane + (m<<5)]);
    #pragma unroll
    for (int m=0;m<8;m++)  hv[m+8] = __bfloat1622float2(h21[lane + (m<<5)]);
    #pragma unroll
    for (int c=0;c<CC;c++) {
        const float2* w2 = (const float2*)(clsW + c*1024);
        float s = 0.f;
        #pragma unroll
        for (int m=0;m<16;m++){
            float2 wv = w2[lane + (m<<5)];
            s += hv[m].x*wv.x + hv[m].y*wv.y;
        }
        #pragma unroll
        for (int o=16;o;o>>=1) s += __shfl_xor_sync(0xffffffffu, s, o);
        if (lane==0) g_EM[(size_t)row*CC + c] = s + clsB[c];
    }
}

// ---------------- fused CRF (numerator + denominator), one warp per batch ----------------
__global__ void crf_kernel(const int* __restrict__ y, const float* __restrict__ trans,
                           const float* __restrict__ cstart, const float* __restrict__ cend)
{
    __shared__ float st[CC*CC];
    if (threadIdx.x < CC*CC) st[threadIdx.x] = trans[threadIdx.x];
    __syncthreads();

    int b = (blockIdx.x << 3) + (threadIdx.x >> 5);
    int lane = threadIdx.x & 31;
    int c = lane < CC ? lane : CC-1;
    float tcol[CC];
    #pragma unroll
    for (int i=0;i<CC;i++) tcol[i] = st[i*CC + c];

    int y0 = y[b*TT];
    int prev = y0 > 0 ? y0 : 0;
    float alpha = cstart[c] + g_EM[(size_t)b*CC + c];
    float sc = __shfl_sync(0xffffffffu, alpha, prev);
    int cnt = (y0 > -1) ? 1 : 0;

    float e_next = g_EM[((size_t)1*BB + b)*CC + c];
    int   y_next = y[b*TT + 1];

    for (int t=1;t<TT;t++) {
        float e  = e_next;
        int   yt = y_next;
        if (t+1 < TT){
            e_next = g_EM[((size_t)(t+1)*BB + b)*CC + c];
            y_next = y[b*TT + t + 1];
        }
        float av[CC]; float mx = -1e30f;
        #pragma unroll
        for (int i=0;i<CC;i++) { av[i] = __shfl_sync(0xffffffffu, alpha, i) + tcol[i]; mx = fmaxf(mx, av[i]); }
        float su = 0.f;
        #pragma unroll
        for (int i=0;i<CC;i++) su += expf(av[i]-mx);
        float nxt = mx + logf(su) + e;
        bool m = (yt > -1);
        if (m) alpha = nxt;
        int tgt = yt > 0 ? yt : 0;
        float etg = __shfl_sync(0xffffffffu, e, tgt);
        sc += (st[prev*CC + tgt] + etg) * (m ? 1.f : 0.f);
        prev = tgt;
        cnt += m ? 1 : 0;
    }
    int se = cnt - 1; if (se < 0) se = 0;
    int yl = y[b*TT + se];
    int lt = yl > 0 ? yl : 0;
    sc += cend[lt];

    float v = alpha + cend[c];
    float mx = -1e30f;
    #pragma unroll
    for (int i=0;i<CC;i++) mx = fmaxf(mx, __shfl_sync(0xffffffffu, v, i));
    float su = 0.f;
    #pragma unroll
    for (int i=0;i<CC;i++) su += expf(__shfl_sync(0xffffffffu, v, i) - mx);
    if (lane==0) g_LLH[b] = sc - (mx + logf(su));
}

// ---------------- final reduction ----------------
__global__ void final_kernel(float* __restrict__ out)
{
    int tid = threadIdx.x;
    float v = g_LLH[tid];
    #pragma unroll
    for (int o=16;o;o>>=1) v += __shfl_xor_sync(0xffffffffu, v, o);
    __shared__ float sr[4];
    if ((tid&31)==0) sr[tid>>5] = v;
    __syncthreads();
    if (tid==0) out[0] = -(sr[0]+sr[1]+sr[2]+sr[3]) / 128.0f;
}

// ---------------- launch ----------------
extern "C" void kernel_launch(void* const* d_in, const int* in_sizes, int n_in,
                              void* d_out, int out_size)
{
    const int*   x        = (const int*)  d_in[0];
    const int*   y        = (const int*)  d_in[1];
    const float* embed    = (const float*)d_in[2];
    const float* w_ih_l0  = (const float*)d_in[3];
    const float* w_hh_l0  = (const float*)d_in[4];
    const float* b_l0     = (const float*)d_in[5];
    const float* w_ih_l1  = (const float*)d_in[6];
    const float* w_hh_l1  = (const float*)d_in[7];
    const float* b_l1     = (const float*)d_in[8];
    const float* cls_w    = (const float*)d_in[9];
    const float* cls_b    = (const float*)d_in[10];
    const float* crf_start= (const float*)d_in[11];
    const float* crf_end  = (const float*)d_in[12];
    const float* crf_trans= (const float*)d_in[13];
    float* out = (float*)d_out;

    const int GEMM_SMEM = 2*(128*64)*2*2;                           // 65536 B
    const int SCAN_SMEM = 32*1024 + 133120 + 20480 + 16384;         // 202752 B
    cudaFuncSetAttribute(gemm_pre_mma, cudaFuncAttributeMaxDynamicSharedMemorySize, GEMM_SMEM);
    cudaFuncSetAttribute(lstm_scan_mma, cudaFuncAttributeMaxDynamicSharedMemorySize, SCAN_SMEM);

    reset_flags<<<1024, 64>>>();
    embed_kernel<<<MM, 128>>>(x, embed);
    convert_weights<<<512, 256>>>(w_ih_l0, w_hh_l0, w_ih_l1, w_hh_l1);

    gemm_pre_mma<<<dim3(32,256), 256, GEMM_SMEM>>>(0, b_l0);
    lstm_scan_mma<<<128, 256, SCAN_SMEM>>>(0);
    gemm_pre_mma<<<dim3(32,256), 256, GEMM_SMEM>>>(1, b_l1);
    lstm_scan_mma<<<128, 256, SCAN_SMEM>>>(1);

    emissions_kernel<<<4096, 256>>>(cls_w, cls_b);
    crf_kernel<<<16, 256>>>(y, crf_trans, crf_start, crf_end);
    final_kernel<<<1, 128>>>(out);
}

// round 13
// speedup vs baseline: 1.2960x; 1.0577x over previous
#include <cuda_runtime.h>
#include <cuda_bf16.h>
#include <math.h>

#define TT 256
#define BB 128
#define CC 9
#define MM (TT*BB)      // 32768 rows

typedef __nv_bfloat16 bf16;

// ---------------- scratch (static device globals; no allocs) ----------------
__device__ bf16  g_X0b[(size_t)MM*512];       // layer0 input, bf16 (T,B,512)
__device__ bf16  g_HA0[(size_t)MM*512];       // layer0 h fwd (T,B,512)
__device__ bf16  g_HA1[(size_t)MM*512];       // layer0 h bwd
__device__ bf16  g_HB0[(size_t)MM*512];       // layer1 h fwd
__device__ bf16  g_HB1[(size_t)MM*512];       // layer1 h bwd
// PRE scan-major: [dir][jg(32)][t*B][64]  (col = gate*16 + (j&15))
__device__ float g_PRE[(size_t)2*32*MM*64];
__device__ bf16  g_WI0b[4096*512];            // w_ih_l0 bf16
__device__ bf16  g_WI1b[(size_t)4096*1024];   // w_ih_l1 bf16
__device__ bf16  g_WH0b[2*2048*512];          // w_hh_l0 bf16
__device__ bf16  g_WH1b[2*2048*512];          // w_hh_l1 bf16
__device__ float g_EM[(size_t)MM*CC];
__device__ float g_LLH[BB];
// per-block done flags: [layer][dir][bh][step][jg*32] (128B apart)
__device__ unsigned g_flags[2][2][2][TT][32*32];

__device__ __forceinline__ float fsig(float x){ return 1.0f/(1.0f+__expf(-x)); }
__device__ __forceinline__ float ftanh(float x){
    float ax = fabsf(x);
    float t = __expf(-2.0f*ax);
    float r = (1.0f - t)/(1.0f + t);
    return copysignf(r, x);
}

// ---------------- PTX helpers ----------------
__device__ __forceinline__ unsigned su32(const void* p){ return (unsigned)__cvta_generic_to_shared(p); }
__device__ __forceinline__ void cp16(unsigned s, const void* g){
    asm volatile("cp.async.cg.shared.global [%0], [%1], 16;\n" :: "r"(s), "l"(g));
}
__device__ __forceinline__ void cpcommit(){ asm volatile("cp.async.commit_group;\n"); }
template<int N> __device__ __forceinline__ void cpwait(){ asm volatile("cp.async.wait_group %0;\n"::"n"(N)); }
__device__ __forceinline__ void ldsm4(unsigned &r0, unsigned &r1, unsigned &r2, unsigned &r3, unsigned addr){
    asm volatile("ldmatrix.sync.aligned.m8n8.x4.shared.b16 {%0,%1,%2,%3}, [%4];\n"
        : "=r"(r0),"=r"(r1),"=r"(r2),"=r"(r3) : "r"(addr));
}
__device__ __forceinline__ void mma16816(float* c, const unsigned* a, unsigned b0, unsigned b1){
    asm volatile("mma.sync.aligned.m16n8k16.row.col.f32.bf16.bf16.f32 "
        "{%0,%1,%2,%3}, {%4,%5,%6,%7}, {%8,%9}, {%0,%1,%2,%3};\n"
        : "+f"(c[0]),"+f"(c[1]),"+f"(c[2]),"+f"(c[3])
        : "r"(a[0]),"r"(a[1]),"r"(a[2]),"r"(a[3]),"r"(b0),"r"(b1));
}
__device__ __forceinline__ void st_release(unsigned* p, unsigned v){
    asm volatile("st.release.gpu.global.u32 [%0], %1;" :: "l"(p), "r"(v) : "memory");
}
__device__ __forceinline__ unsigned load_acq(const unsigned* p){
    unsigned v;
    asm volatile("ld.acquire.gpu.global.u32 %0, [%1];" : "=r"(v) : "l"(p) : "memory");
    return v;
}
__device__ __forceinline__ void mbar_init(unsigned m, unsigned cnt){
    asm volatile("mbarrier.init.shared.b64 [%0], %1;" :: "r"(m), "r"(cnt) : "memory");
}
__device__ __forceinline__ void mbar_expect(unsigned m, unsigned bytes){
    asm volatile("mbarrier.arrive.expect_tx.shared.b64 _, [%0], %1;" :: "r"(m), "r"(bytes) : "memory");
}
__device__ __forceinline__ void bulkcp(unsigned dst, const void* src, unsigned bytes, unsigned m){
    asm volatile("cp.async.bulk.shared::cta.global.mbarrier::complete_tx::bytes [%0], [%1], %2, [%3];"
        :: "r"(dst), "l"(src), "r"(bytes), "r"(m) : "memory");
}
__device__ __forceinline__ void mbar_wait(unsigned m, unsigned parity){
    asm volatile(
        "{\n\t.reg .pred P;\n\t"
        "WL%=:\n\t"
        "mbarrier.try_wait.parity.acquire.cta.shared::cta.b64 P, [%0], %1, 0x989680;\n\t"
        "@P bra WD%=;\n\t"
        "bra WL%=;\n\t"
        "WD%=:\n\t}"
        :: "r"(m), "r"(parity) : "memory");
}
__device__ __forceinline__ void bar_named(int id, int nthreads){
    asm volatile("bar.sync %0, %1;" :: "r"(id), "r"(nthreads) : "memory");
}

// ---------------- reset flags (once per launch; graph-replay safe) ----------------
// total flag slots = 2*2*2*256*32 = 65536; grid 1024 x 64 threads
__global__ void reset_flags(){
    unsigned slot = blockIdx.x*64u + threadIdx.x;
    ((unsigned*)g_flags)[slot*32u] = 0u;
}

// ---------------- embedding lookup + norm clip -> bf16 ----------------
__global__ void embed_kernel(const int* __restrict__ x, const float* __restrict__ embed)
{
    int r = blockIdx.x;            // r = t*BB + b
    int t = r >> 7;
    int b = r & 127;
    int v = x[b*TT + t];
    const float* e = embed + (size_t)v * 512;
    int tid = threadIdx.x;         // 128
    float4 ev = ((const float4*)e)[tid];
    float ss = ev.x*ev.x + ev.y*ev.y + ev.z*ev.z + ev.w*ev.w;
    #pragma unroll
    for (int o = 16; o; o >>= 1) ss += __shfl_xor_sync(0xffffffffu, ss, o);
    __shared__ float sred[4];
    if ((tid & 31) == 0) sred[tid>>5] = ss;
    __syncthreads();
    float nrm = sqrtf(sred[0]+sred[1]+sred[2]+sred[3]);
    float sc = (nrm > 1.0f) ? 1.0f/(nrm + 1e-7f) : 1.0f;
    __nv_bfloat162 p0 = __floats2bfloat162_rn(ev.x*sc, ev.y*sc);
    __nv_bfloat162 p1 = __floats2bfloat162_rn(ev.z*sc, ev.w*sc);
    __nv_bfloat162* op = (__nv_bfloat162*)(g_X0b + (size_t)r*512);
    op[tid*2]   = p0;
    op[tid*2+1] = p1;
}

// ---------------- weight fp32 -> bf16 conversion (vectorized) ----------------
__device__ __forceinline__ void conv8(bf16* dst, const float* src, size_t i8){
    const float4* s4 = (const float4*)(src + i8*8);
    float4 a = s4[0], b = s4[1];
    __nv_bfloat162 q0 = __floats2bfloat162_rn(a.x, a.y);
    __nv_bfloat162 q1 = __floats2bfloat162_rn(a.z, a.w);
    __nv_bfloat162 q2 = __floats2bfloat162_rn(b.x, b.y);
    __nv_bfloat162 q3 = __floats2bfloat162_rn(b.z, b.w);
    uint4 o; o.x = *(unsigned*)&q0; o.y = *(unsigned*)&q1; o.z = *(unsigned*)&q2; o.w = *(unsigned*)&q3;
    *(uint4*)(dst + i8*8) = o;
}
__global__ void convert_weights(const float* __restrict__ wi0, const float* __restrict__ wh0,
                                const float* __restrict__ wi1, const float* __restrict__ wh1)
{
    const size_t N0 = 2u*2048*512/8;
    const size_t N1 = 2u*2048*512/8;
    const size_t N2 = 2u*2048*1024/8;
    const size_t N3 = 2u*2048*512/8;
    size_t total = N0+N1+N2+N3;
    size_t stride = (size_t)gridDim.x*blockDim.x;
    for (size_t i = (size_t)blockIdx.x*blockDim.x + threadIdx.x; i < total; i += stride) {
        if (i < N0)                 conv8(g_WI0b, wi0, i);
        else if (i < N0+N1)         conv8(g_WH0b, wh0, i-N0);
        else if (i < N0+N1+N2)      conv8(g_WI1b, wi1, i-N0-N1);
        else                        conv8(g_WH1b, wh1, i-N0-N1-N2);
    }
}

// ---------------- bf16 tensor-core input-projection GEMM ----------------
// Epilogue writes PRE in scan-major layout [dir][jg][m][gate*16+jj]
__global__ __launch_bounds__(256) void gemm_pre_mma(int layer, const float* __restrict__ bias)
{
    const bf16* A0 = layer ? g_HA0 : g_X0b;
    const bf16* A1 = layer ? g_HA1 : g_X0b;
    const bf16* W  = layer ? g_WI1b : g_WI0b;
    const int K  = layer ? 1024 : 512;
    const int m0 = blockIdx.y << 7;
    const int n0 = blockIdx.x << 7;

    extern __shared__ char smraw[];
    bf16* As = (bf16*)smraw;            // 2 stages x [128][64]
    bf16* Bs = As + 2*128*64;
    unsigned AsB = su32(As), BsB = su32(Bs);

    const int tid = threadIdx.x;
    const int warp = tid>>5, lane = tid&31;
    const int wm = warp>>2, wn = warp&3;

    float acc[4][4][4];
    #pragma unroll
    for (int i=0;i<4;i++)
        #pragma unroll
        for (int j=0;j<4;j++)
            #pragma unroll
            for (int k=0;k<4;k++) acc[i][j][k]=0.f;

    const int srow = tid>>1;
    const int skc0 = (tid&1)*4;
    const size_t arow = (size_t)(m0+srow)*512;
    const bf16* Wg = W + (size_t)(n0+srow)*K + skc0*8;
    unsigned AsRow = AsB + srow*128;
    unsigned BsRow = BsB + srow*128;

    const int iters = K >> 6;
    #pragma unroll
    for (int i=0;i<4;i++){
        int kc = skc0+i;
        unsigned sw = ((kc ^ (srow&7))<<4);
        cp16(AsRow + sw, A0 + arow + skc0*8 + i*8);
        cp16(BsRow + sw, Wg + i*8);
    }
    cpcommit();

    for (int kt=0; kt<iters; kt++){
        int s = kt&1;
        if (kt+1 < iters){
            int koff = (kt+1)<<6;
            const bf16* Asrc = (koff < 512) ? (A0 + arow + koff) : (A1 + arow + koff - 512);
            #pragma unroll
            for (int i=0;i<4;i++){
                int kc = skc0+i;
                unsigned sw = ((s^1)*128*128) + ((kc ^ (srow&7))<<4);
                cp16(AsRow + sw, Asrc + skc0*8 + i*8);
                cp16(BsRow + sw, Wg + koff + i*8);
            }
            cpcommit();
            cpwait<1>();
        } else {
            cpwait<0>();
        }
        __syncthreads();

        unsigned Ab = AsB + s*128*128;
        unsigned Bb = BsB + s*128*128;
        #pragma unroll
        for (int kk=0; kk<4; kk++){
            unsigned af[4][4];
            #pragma unroll
            for (int mt=0; mt<4; mt++){
                int row = wm*64 + mt*16 + (lane&15);
                int ch  = kk*2 + (lane>>4);
                ldsm4(af[mt][0],af[mt][1],af[mt][2],af[mt][3],
                      Ab + row*128 + ((ch ^ (row&7))<<4));
            }
            unsigned bfr[2][4];
            #pragma unroll
            for (int np=0; np<2; np++){
                int row = wn*32 + np*16 + (lane&7) + ((lane>=16)?8:0);
                int ch  = kk*2 + ((lane>>3)&1);
                ldsm4(bfr[np][0],bfr[np][1],bfr[np][2],bfr[np][3],
                      Bb + row*128 + ((ch ^ (row&7))<<4));
            }
            #pragma unroll
            for (int mt=0; mt<4; mt++)
                #pragma unroll
                for (int nt=0; nt<4; nt++)
                    mma16816(acc[mt][nt], af[mt], bfr[nt>>1][(nt&1)*2], bfr[nt>>1][(nt&1)*2+1]);
        }
        __syncthreads();
    }

    const int r = lane>>2, cp2 = (lane&3)*2;
    #pragma unroll
    for (int mt=0; mt<4; mt++){
        #pragma unroll
        for (int nt=0; nt<4; nt++){
            int m = m0 + wm*64 + mt*16 + r;
            int n = n0 + wn*32 + nt*8 + cp2;
            int dir  = n >> 11;
            int c2   = n & 2047;
            int gate = c2 >> 9;
            int j    = c2 & 511;
            int jg   = j >> 4;
            int jj   = j & 15;
            float2 bv = *(const float2*)(bias + n);
            float2 o0 = make_float2(acc[mt][nt][0]+bv.x, acc[mt][nt][1]+bv.y);
            float2 o1 = make_float2(acc[mt][nt][2]+bv.x, acc[mt][nt][3]+bv.y);
            size_t base = (((size_t)(dir*32 + jg)*MM) + m)*64 + gate*16 + jj;
            *(float2*)&g_PRE[base]        = o0;
            *(float2*)&g_PRE[base + 8*64] = o1;   // row m+8
        }
    }
}

// ---------------- persistent LSTM scan: 128 blocks, (16 j) x (batch-half) tiles ----------------
// block = (dir, jg 0..31, bh 0..1). Whh slice 64 rows x 512 (64KB SMEM).
// h stage per step = 64 rows x 1KB = 64KB (half traffic); fan-in = 32 producers of same bh.
__global__ __launch_bounds__(256, 1) void lstm_scan_mma(int layer)
{
    extern __shared__ char smraw[];
    bf16*  Ws   = (bf16*)smraw;                              // 64 rows x 1024B = 65536
    char*  Asm  = smraw + 65536;                             // 64 rows x 1040B = 66560
    float* zb   = (float*)(smraw + 65536 + 66560);           // [64][72] = 18432
    float* sPre = (float*)(smraw + 65536 + 66560 + 18432);   // [64][64] = 16384
    __shared__ __align__(8) unsigned long long mbars[2];     // H, PRE

    const int bid = blockIdx.x;
    const int dir = bid >> 6;
    const int rem = bid & 63;
    const int jg  = rem >> 1;
    const int bh  = rem & 1;
    const int j0  = jg << 4;
    bf16* Hbuf = layer ? (dir ? g_HB1 : g_HB0)
                       : (dir ? g_HA1 : g_HA0);
    const bf16* WH = layer ? g_WH1b : g_WH0b;
    const int tid = threadIdx.x;
    const int warp = tid>>5, lane = tid&31;
    const int wm = warp>>2, wn = warp&3;
    unsigned WsB = su32(Ws), AsB = su32(Asm), sPreB = su32(sPre);
    unsigned mbH = su32(&mbars[0]), mbP = su32(&mbars[1]);

    if (tid == 0){
        mbar_init(mbH, 1);
        mbar_init(mbP, 1);
        asm volatile("fence.proxy.async.shared::cta;" ::: "memory");
    }
    // ---- load Whh slice (64 rows x 512) once, swizzled; row n' = gate*16+jj ----
    {
        const bf16* wb = WH + (size_t)dir*2048*512;
        int rr  = tid >> 2;                 // n' 0..63
        int kc0 = (tid & 3) << 4;           // 16 chunks each
        int wrow = ((rr>>4)<<9) + j0 + (rr & 15);   // gate*512 + j0 + jj
        const bf16* gp = wb + (size_t)wrow*512;
        unsigned srw = WsB + rr*1024;
        #pragma unroll
        for (int i=0;i<16;i++){
            int kc = kc0+i;
            cp16(srw + ((kc ^ (rr&7))<<4), gp + kc*8);
        }
        cpcommit(); cpwait<0>();
    }
    __syncthreads();

    // gates map: thread -> (local b = tid>>2, 4 j's at (tid&3)*4), c in registers
    const int bl = tid>>2;
    const int jq = (tid&3)*4;
    float creg[4] = {0.f, 0.f, 0.f, 0.f};

    for (int s=0; s<TT; s++){
        const int t_out = dir ? (TT-1-s) : s;

        // ---- PRE: one contiguous 16KB bulk copy, issued pre-wait ----
        if (tid == 0){
            const float* prer = g_PRE + (((size_t)(dir*32 + jg)*MM) + (size_t)t_out*BB + bh*64)*64;
            mbar_expect(mbP, 16384u);
            bulkcp(sPreB, prer, 16384u, mbP);
        }

        float acc[2][2][4];
        #pragma unroll
        for (int i=0;i<2;i++)
            #pragma unroll
            for (int j=0;j<2;j++)
                #pragma unroll
                for (int k=0;k<4;k++) acc[i][j][k]=0.f;

        if (s > 0){
            const unsigned pH = (unsigned)((s-1)&1);
            const int t_prev = dir ? (t_out+1) : (s-1);
            const bf16* hbase = Hbuf + ((size_t)t_prev*BB + bh*64)*512;

            if (tid < 128){
                // threads 0..31 poll the 32 producer flags of (dir, bh)
                if (tid < 32){
                    const unsigned* fp = &g_flags[layer][dir][bh][s-1][tid*32];
                    while (load_acq(fp) == 0u) { }
                    if (tid == 0) mbar_expect(mbH, 65536u);
                }
                bar_named(1, 128);
                // 128 threads each stage 512B (64 rows x 2 chunks)
                int row = tid >> 1, half = tid & 1;
                bulkcp(AsB + row*1040 + half*512,
                       hbase + (size_t)row*512 + half*256, 512u, mbH);
            }

            mbar_wait(mbH, pH);

            // mma M=64 x N=64 x K=512
            #pragma unroll 4
            for (int kk=0; kk<32; kk++){
                unsigned af[2][4];
                #pragma unroll
                for (int mt=0; mt<2; mt++){
                    int row = wm*32 + mt*16 + (lane&15);
                    int ch  = kk*2 + (lane>>4);
                    ldsm4(af[mt][0],af[mt][1],af[mt][2],af[mt][3],
                          AsB + row*1040 + ch*16);
                }
                unsigned bfr[4];
                {
                    int row = wn*16 + (lane&7) + ((lane>=16)?8:0);
                    int ch  = kk*2 + ((lane>>3)&1);
                    ldsm4(bfr[0],bfr[1],bfr[2],bfr[3],
                          WsB + row*1024 + ((ch ^ (row&7))<<4));
                }
                #pragma unroll
                for (int mt=0; mt<2; mt++){
                    mma16816(acc[mt][0], af[mt], bfr[0], bfr[1]);
                    mma16816(acc[mt][1], af[mt], bfr[2], bfr[3]);
                }
            }
        }
        __syncthreads();

        // ---- exchange z through smem (rows 64, stride 72 floats) ----
        {
            const int r = lane>>2, cq = (lane&3)*2;
            #pragma unroll
            for (int mt=0; mt<2; mt++)
                #pragma unroll
                for (int nt=0; nt<2; nt++){
                    int mr = wm*32 + mt*16 + r;
                    int nc = wn*16 + nt*8 + cq;
                    zb[mr*72 + nc]       = acc[mt][nt][0];
                    zb[mr*72 + nc+1]     = acc[mt][nt][1];
                    zb[(mr+8)*72 + nc]   = acc[mt][nt][2];
                    zb[(mr+8)*72 + nc+1] = acc[mt][nt][3];
                }
        }
        mbar_wait(mbP, (unsigned)(s&1));
        __syncthreads();

        // ---- gates: thread -> (bl, 4 j's), c in registers ----
        {
            const float* zr = zb + bl*72;
            const float* sp = sPre + bl*64;
            float4 zi = *(const float4*)(zr + jq);
            float4 zf = *(const float4*)(zr + 16 + jq);
            float4 zg = *(const float4*)(zr + 32 + jq);
            float4 zo = *(const float4*)(zr + 48 + jq);
            float4 pi = *(const float4*)(sp + jq);
            float4 pf = *(const float4*)(sp + 16 + jq);
            float4 pg = *(const float4*)(sp + 32 + jq);
            float4 po = *(const float4*)(sp + 48 + jq);

            float ho[4];
            float zis[4]={zi.x+pi.x, zi.y+pi.y, zi.z+pi.z, zi.w+pi.w};
            float zfs[4]={zf.x+pf.x, zf.y+pf.y, zf.z+pf.z, zf.w+pf.w};
            float zgs[4]={zg.x+pg.x, zg.y+pg.y, zg.z+pg.z, zg.w+pg.w};
            float zos[4]={zo.x+po.x, zo.y+po.y, zo.z+po.z, zo.w+po.w};
            #pragma unroll
            for (int u=0;u<4;u++){
                float fi=fsig(zis[u]), ff=fsig(zfs[u]), fg=ftanh(zgs[u]), fo=fsig(zos[u]);
                creg[u] = ff*creg[u] + fi*fg;
                ho[u] = fo*ftanh(creg[u]);
            }
            __nv_bfloat162 p0 = __floats2bfloat162_rn(ho[0],ho[1]);
            __nv_bfloat162 p1 = __floats2bfloat162_rn(ho[2],ho[3]);
            uint2 uv; uv.x = *(unsigned*)&p0; uv.y = *(unsigned*)&p1;
            *(uint2*)&Hbuf[((size_t)t_out*BB + bh*64 + bl)*512 + j0 + jq] = uv;
        }

        __syncthreads();
        if (tid==0) st_release(&g_flags[layer][dir][bh][s][jg*32], 1u);
    }
}

// ---------------- classifier emissions (h in split bf16 buffers) ----------------
__global__ void emissions_kernel(const float* __restrict__ clsW, const float* __restrict__ clsB)
{
    int warp = threadIdx.x >> 5, lane = threadIdx.x & 31;
    int row = (blockIdx.x << 3) + warp;
    const __nv_bfloat162* h20 = (const __nv_bfloat162*)(g_HB0 + (size_t)row * 512);
    const __nv_bfloat162* h21 = (const __nv_bfloat162*)(g_HB1 + (size_t)row * 512);
    float2 hv[16];
    #pragma unroll
    for (int m=0;m<8;m++)  hv[m]   = __bfloat1622float2(h20[lane + (m<<5)]);
    #pragma unroll
    for (int m=0;m<8;m++)  hv[m+8] = __bfloat1622float2(h21[lane + (m<<5)]);
    #pragma unroll
    for (int c=0;c<CC;c++) {
        const float2* w2 = (const float2*)(clsW + c*1024);
        float s = 0.f;
        #pragma unroll
        for (int m=0;m<16;m++){
            float2 wv = w2[lane + (m<<5)];
            s += hv[m].x*wv.x + hv[m].y*wv.y;
        }
        #pragma unroll
        for (int o=16;o;o>>=1) s += __shfl_xor_sync(0xffffffffu, s, o);
        if (lane==0) g_EM[(size_t)row*CC + c] = s + clsB[c];
    }
}

// ---------------- fused CRF (numerator + denominator), one warp per batch ----------------
__global__ void crf_kernel(const int* __restrict__ y, const float* __restrict__ trans,
                           const float* __restrict__ cstart, const float* __restrict__ cend)
{
    __shared__ float st[CC*CC];
    if (threadIdx.x < CC*CC) st[threadIdx.x] = trans[threadIdx.x];
    __syncthreads();

    int b = (blockIdx.x << 3) + (threadIdx.x >> 5);
    int lane = threadIdx.x & 31;
    int c = lane < CC ? lane : CC-1;
    float tcol[CC];
    #pragma unroll
    for (int i=0;i<CC;i++) tcol[i] = st[i*CC + c];

    int y0 = y[b*TT];
    int prev = y0 > 0 ? y0 : 0;
    float alpha = cstart[c] + g_EM[(size_t)b*CC + c];
    float sc = __shfl_sync(0xffffffffu, alpha, prev);
    int cnt = (y0 > -1) ? 1 : 0;

    float e_next = g_EM[((size_t)1*BB + b)*CC + c];
    int   y_next = y[b*TT + 1];

    for (int t=1;t<TT;t++) {
        float e  = e_next;
        int   yt = y_next;
        if (t+1 < TT){
            e_next = g_EM[((size_t)(t+1)*BB + b)*CC + c];
            y_next = y[b*TT + t + 1];
        }
        float av[CC]; float mx = -1e30f;
        #pragma unroll
        for (int i=0;i<CC;i++) { av[i] = __shfl_sync(0xffffffffu, alpha, i) + tcol[i]; mx = fmaxf(mx, av[i]); }
        float su = 0.f;
        #pragma unroll
        for (int i=0;i<CC;i++) su += expf(av[i]-mx);
        float nxt = mx + logf(su) + e;
        bool m = (yt > -1);
        if (m) alpha = nxt;
        int tgt = yt > 0 ? yt : 0;
        float etg = __shfl_sync(0xffffffffu, e, tgt);
        sc += (st[prev*CC + tgt] + etg) * (m ? 1.f : 0.f);
        prev = tgt;
        cnt += m ? 1 : 0;
    }
    int se = cnt - 1; if (se < 0) se = 0;
    int yl = y[b*TT + se];
    int lt = yl > 0 ? yl : 0;
    sc += cend[lt];

    float v = alpha + cend[c];
    float mx = -1e30f;
    #pragma unroll
    for (int i=0;i<CC;i++) mx = fmaxf(mx, __shfl_sync(0xffffffffu, v, i));
    float su = 0.f;
    #pragma unroll
    for (int i=0;i<CC;i++) su += expf(__shfl_sync(0xffffffffu, v, i) - mx);
    if (lane==0) g_LLH[b] = sc - (mx + logf(su));
}

// ---------------- final reduction ----------------
__global__ void final_kernel(float* __restrict__ out)
{
    int tid = threadIdx.x;
    float v = g_LLH[tid];
    #pragma unroll
    for (int o=16;o;o>>=1) v += __shfl_xor_sync(0xffffffffu, v, o);
    __shared__ float sr[4];
    if ((tid&31)==0) sr[tid>>5] = v;
    __syncthreads();
    if (tid==0) out[0] = -(sr[0]+sr[1]+sr[2]+sr[3]) / 128.0f;
}

// ---------------- launch ----------------
extern "C" void kernel_launch(void* const* d_in, const int* in_sizes, int n_in,
                              void* d_out, int out_size)
{
    const int*   x        = (const int*)  d_in[0];
    const int*   y        = (const int*)  d_in[1];
    const float* embed    = (const float*)d_in[2];
    const float* w_ih_l0  = (const float*)d_in[3];
    const float* w_hh_l0  = (const float*)d_in[4];
    const float* b_l0     = (const float*)d_in[5];
    const float* w_ih_l1  = (const float*)d_in[6];
    const float* w_hh_l1  = (const float*)d_in[7];
    const float* b_l1     = (const float*)d_in[8];
    const float* cls_w    = (const float*)d_in[9];
    const float* cls_b    = (const float*)d_in[10];
    const float* crf_start= (const float*)d_in[11];
    const float* crf_end  = (const float*)d_in[12];
    const float* crf_trans= (const float*)d_in[13];
    float* out = (float*)d_out;

    const int GEMM_SMEM = 2*(128*64)*2*2;                           // 65536 B
    const int SCAN_SMEM = 65536 + 66560 + 18432 + 16384;            // 166912 B
    cudaFuncSetAttribute(gemm_pre_mma, cudaFuncAttributeMaxDynamicSharedMemorySize, GEMM_SMEM);
    cudaFuncSetAttribute(lstm_scan_mma, cudaFuncAttributeMaxDynamicSharedMemorySize, SCAN_SMEM);

    reset_flags<<<1024, 64>>>();
    embed_kernel<<<MM, 128>>>(x, embed);
    convert_weights<<<512, 256>>>(w_ih_l0, w_hh_l0, w_ih_l1, w_hh_l1);

    gemm_pre_mma<<<dim3(32,256), 256, GEMM_SMEM>>>(0, b_l0);
    lstm_scan_mma<<<128, 256, SCAN_SMEM>>>(0);
    gemm_pre_mma<<<dim3(32,256), 256, GEMM_SMEM>>>(1, b_l1);
    lstm_scan_mma<<<128, 256, SCAN_SMEM>>>(1);

    emissions_kernel<<<4096, 256>>>(cls_w, cls_b);
    crf_kernel<<<16, 256>>>(y, crf_trans, crf_start, crf_end);
    final_kernel<<<1, 128>>>(out);
}

// round 14
// speedup vs baseline: 1.3282x; 1.0248x over previous
#include <cuda_runtime.h>
#include <cuda_bf16.h>
#include <math.h>

#define TT 256
#define BB 128
#define CC 9
#define MM (TT*BB)      // 32768 rows

typedef __nv_bfloat16 bf16;

// ---------------- scratch (static device globals; no allocs) ----------------
__device__ bf16  g_X0b[(size_t)MM*512];       // layer0 input, bf16 (T,B,512)
__device__ bf16  g_HA0[(size_t)MM*512];       // layer0 h fwd (T,B,512)
__device__ bf16  g_HA1[(size_t)MM*512];       // layer0 h bwd
__device__ bf16  g_HB0[(size_t)MM*512];       // layer1 h fwd
__device__ bf16  g_HB1[(size_t)MM*512];       // layer1 h bwd
// PRE scan-major: [dir][jg(16)][t*B][128]  (col = gate*32 + (j&31))
__device__ float g_PRE[(size_t)2*16*MM*128];
__device__ bf16  g_WI0b[4096*512];            // w_ih_l0 bf16
__device__ bf16  g_WI1b[(size_t)4096*1024];   // w_ih_l1 bf16
__device__ bf16  g_WH0b[2*2048*512];          // w_hh_l0 bf16
__device__ bf16  g_WH1b[2*2048*512];          // w_hh_l1 bf16
__device__ float g_EM[(size_t)MM*CC];
__device__ float g_LLH[BB];
// per-block done flags: [layer][dir][bq(4)][step][jg(16)*32] (128B apart)
__device__ unsigned g_flags[2][2][4][TT][16*32];

__device__ __forceinline__ float fsig(float x){ return 1.0f/(1.0f+__expf(-x)); }
__device__ __forceinline__ float ftanh(float x){
    float ax = fabsf(x);
    float t = __expf(-2.0f*ax);
    float r = (1.0f - t)/(1.0f + t);
    return copysignf(r, x);
}

// ---------------- PTX helpers ----------------
__device__ __forceinline__ unsigned su32(const void* p){ return (unsigned)__cvta_generic_to_shared(p); }
__device__ __forceinline__ void cp16(unsigned s, const void* g){
    asm volatile("cp.async.cg.shared.global [%0], [%1], 16;\n" :: "r"(s), "l"(g));
}
__device__ __forceinline__ void cpcommit(){ asm volatile("cp.async.commit_group;\n"); }
template<int N> __device__ __forceinline__ void cpwait(){ asm volatile("cp.async.wait_group %0;\n"::"n"(N)); }
__device__ __forceinline__ void ldsm4(unsigned &r0, unsigned &r1, unsigned &r2, unsigned &r3, unsigned addr){
    asm volatile("ldmatrix.sync.aligned.m8n8.x4.shared.b16 {%0,%1,%2,%3}, [%4];\n"
        : "=r"(r0),"=r"(r1),"=r"(r2),"=r"(r3) : "r"(addr));
}
__device__ __forceinline__ void mma16816(float* c, const unsigned* a, unsigned b0, unsigned b1){
    asm volatile("mma.sync.aligned.m16n8k16.row.col.f32.bf16.bf16.f32 "
        "{%0,%1,%2,%3}, {%4,%5,%6,%7}, {%8,%9}, {%0,%1,%2,%3};\n"
        : "+f"(c[0]),"+f"(c[1]),"+f"(c[2]),"+f"(c[3])
        : "r"(a[0]),"r"(a[1]),"r"(a[2]),"r"(a[3]),"r"(b0),"r"(b1));
}
__device__ __forceinline__ void st_release(unsigned* p, unsigned v){
    asm volatile("st.release.gpu.global.u32 [%0], %1;" :: "l"(p), "r"(v) : "memory");
}
__device__ __forceinline__ unsigned load_acq(const unsigned* p){
    unsigned v;
    asm volatile("ld.acquire.gpu.global.u32 %0, [%1];" : "=r"(v) : "l"(p) : "memory");
    return v;
}
__device__ __forceinline__ void mbar_init(unsigned m, unsigned cnt){
    asm volatile("mbarrier.init.shared.b64 [%0], %1;" :: "r"(m), "r"(cnt) : "memory");
}
__device__ __forceinline__ void mbar_expect(unsigned m, unsigned bytes){
    asm volatile("mbarrier.arrive.expect_tx.shared.b64 _, [%0], %1;" :: "r"(m), "r"(bytes) : "memory");
}
__device__ __forceinline__ void bulkcp(unsigned dst, const void* src, unsigned bytes, unsigned m){
    asm volatile("cp.async.bulk.shared::cta.global.mbarrier::complete_tx::bytes [%0], [%1], %2, [%3];"
        :: "r"(dst), "l"(src), "r"(bytes), "r"(m) : "memory");
}
__device__ __forceinline__ void mbar_wait(unsigned m, unsigned parity){
    asm volatile(
        "{\n\t.reg .pred P;\n\t"
        "WL%=:\n\t"
        "mbarrier.try_wait.parity.acquire.cta.shared::cta.b64 P, [%0], %1, 0x989680;\n\t"
        "@P bra WD%=;\n\t"
        "bra WL%=;\n\t"
        "WD%=:\n\t}"
        :: "r"(m), "r"(parity) : "memory");
}
__device__ __forceinline__ void bar_named(int id, int nthreads){
    asm volatile("bar.sync %0, %1;" :: "r"(id), "r"(nthreads) : "memory");
}

// ---------------- reset flags (once per launch; graph-replay safe) ----------------
// total flag slots = 2*2*4*256*16 = 65536; grid 1024 x 64 threads
__global__ void reset_flags(){
    unsigned slot = blockIdx.x*64u + threadIdx.x;
    ((unsigned*)g_flags)[slot*32u] = 0u;
}

// ---------------- embedding lookup + norm clip -> bf16 ----------------
__global__ void embed_kernel(const int* __restrict__ x, const float* __restrict__ embed)
{
    int r = blockIdx.x;            // r = t*BB + b
    int t = r >> 7;
    int b = r & 127;
    int v = x[b*TT + t];
    const float* e = embed + (size_t)v * 512;
    int tid = threadIdx.x;         // 128
    float4 ev = ((const float4*)e)[tid];
    float ss = ev.x*ev.x + ev.y*ev.y + ev.z*ev.z + ev.w*ev.w;
    #pragma unroll
    for (int o = 16; o; o >>= 1) ss += __shfl_xor_sync(0xffffffffu, ss, o);
    __shared__ float sred[4];
    if ((tid & 31) == 0) sred[tid>>5] = ss;
    __syncthreads();
    float nrm = sqrtf(sred[0]+sred[1]+sred[2]+sred[3]);
    float sc = (nrm > 1.0f) ? 1.0f/(nrm + 1e-7f) : 1.0f;
    __nv_bfloat162 p0 = __floats2bfloat162_rn(ev.x*sc, ev.y*sc);
    __nv_bfloat162 p1 = __floats2bfloat162_rn(ev.z*sc, ev.w*sc);
    __nv_bfloat162* op = (__nv_bfloat162*)(g_X0b + (size_t)r*512);
    op[tid*2]   = p0;
    op[tid*2+1] = p1;
}

// ---------------- weight fp32 -> bf16 conversion (vectorized) ----------------
__device__ __forceinline__ void conv8(bf16* dst, const float* src, size_t i8){
    const float4* s4 = (const float4*)(src + i8*8);
    float4 a = s4[0], b = s4[1];
    __nv_bfloat162 q0 = __floats2bfloat162_rn(a.x, a.y);
    __nv_bfloat162 q1 = __floats2bfloat162_rn(a.z, a.w);
    __nv_bfloat162 q2 = __floats2bfloat162_rn(b.x, b.y);
    __nv_bfloat162 q3 = __floats2bfloat162_rn(b.z, b.w);
    uint4 o; o.x = *(unsigned*)&q0; o.y = *(unsigned*)&q1; o.z = *(unsigned*)&q2; o.w = *(unsigned*)&q3;
    *(uint4*)(dst + i8*8) = o;
}
__global__ void convert_weights(const float* __restrict__ wi0, const float* __restrict__ wh0,
                                const float* __restrict__ wi1, const float* __restrict__ wh1)
{
    const size_t N0 = 2u*2048*512/8;
    const size_t N1 = 2u*2048*512/8;
    const size_t N2 = 2u*2048*1024/8;
    const size_t N3 = 2u*2048*512/8;
    size_t total = N0+N1+N2+N3;
    size_t stride = (size_t)gridDim.x*blockDim.x;
    for (size_t i = (size_t)blockIdx.x*blockDim.x + threadIdx.x; i < total; i += stride) {
        if (i < N0)                 conv8(g_WI0b, wi0, i);
        else if (i < N0+N1)         conv8(g_WH0b, wh0, i-N0);
        else if (i < N0+N1+N2)      conv8(g_WI1b, wi1, i-N0-N1);
        else                        conv8(g_WH1b, wh1, i-N0-N1-N2);
    }
}

// ---------------- bf16 tensor-core input-projection GEMM ----------------
// Epilogue writes PRE in scan-major layout [dir][jg][m][gate*32+jj]
__global__ __launch_bounds__(256) void gemm_pre_mma(int layer, const float* __restrict__ bias)
{
    const bf16* A0 = layer ? g_HA0 : g_X0b;
    const bf16* A1 = layer ? g_HA1 : g_X0b;
    const bf16* W  = layer ? g_WI1b : g_WI0b;
    const int K  = layer ? 1024 : 512;
    const int m0 = blockIdx.y << 7;
    const int n0 = blockIdx.x << 7;

    extern __shared__ char smraw[];
    bf16* As = (bf16*)smraw;            // 2 stages x [128][64]
    bf16* Bs = As + 2*128*64;
    unsigned AsB = su32(As), BsB = su32(Bs);

    const int tid = threadIdx.x;
    const int warp = tid>>5, lane = tid&31;
    const int wm = warp>>2, wn = warp&3;

    float acc[4][4][4];
    #pragma unroll
    for (int i=0;i<4;i++)
        #pragma unroll
        for (int j=0;j<4;j++)
            #pragma unroll
            for (int k=0;k<4;k++) acc[i][j][k]=0.f;

    const int srow = tid>>1;
    const int skc0 = (tid&1)*4;
    const size_t arow = (size_t)(m0+srow)*512;
    const bf16* Wg = W + (size_t)(n0+srow)*K + skc0*8;
    unsigned AsRow = AsB + srow*128;
    unsigned BsRow = BsB + srow*128;

    const int iters = K >> 6;
    #pragma unroll
    for (int i=0;i<4;i++){
        int kc = skc0+i;
        unsigned sw = ((kc ^ (srow&7))<<4);
        cp16(AsRow + sw, A0 + arow + skc0*8 + i*8);
        cp16(BsRow + sw, Wg + i*8);
    }
    cpcommit();

    for (int kt=0; kt<iters; kt++){
        int s = kt&1;
        if (kt+1 < iters){
            int koff = (kt+1)<<6;
            const bf16* Asrc = (koff < 512) ? (A0 + arow + koff) : (A1 + arow + koff - 512);
            #pragma unroll
            for (int i=0;i<4;i++){
                int kc = skc0+i;
                unsigned sw = ((s^1)*128*128) + ((kc ^ (srow&7))<<4);
                cp16(AsRow + sw, Asrc + skc0*8 + i*8);
                cp16(BsRow + sw, Wg + koff + i*8);
            }
            cpcommit();
            cpwait<1>();
        } else {
            cpwait<0>();
        }
        __syncthreads();

        unsigned Ab = AsB + s*128*128;
        unsigned Bb = BsB + s*128*128;
        #pragma unroll
        for (int kk=0; kk<4; kk++){
            unsigned af[4][4];
            #pragma unroll
            for (int mt=0; mt<4; mt++){
                int row = wm*64 + mt*16 + (lane&15);
                int ch  = kk*2 + (lane>>4);
                ldsm4(af[mt][0],af[mt][1],af[mt][2],af[mt][3],
                      Ab + row*128 + ((ch ^ (row&7))<<4));
            }
            unsigned bfr[2][4];
            #pragma unroll
            for (int np=0; np<2; np++){
                int row = wn*32 + np*16 + (lane&7) + ((lane>=16)?8:0);
                int ch  = kk*2 + ((lane>>3)&1);
                ldsm4(bfr[np][0],bfr[np][1],bfr[np][2],bfr[np][3],
                      Bb + row*128 + ((ch ^ (row&7))<<4));
            }
            #pragma unroll
            for (int mt=0; mt<4; mt++)
                #pragma unroll
                for (int nt=0; nt<4; nt++)
                    mma16816(acc[mt][nt], af[mt], bfr[nt>>1][(nt&1)*2], bfr[nt>>1][(nt&1)*2+1]);
        }
        __syncthreads();
    }

    const int r = lane>>2, cp2 = (lane&3)*2;
    #pragma unroll
    for (int mt=0; mt<4; mt++){
        #pragma unroll
        for (int nt=0; nt<4; nt++){
            int m = m0 + wm*64 + mt*16 + r;
            int n = n0 + wn*32 + nt*8 + cp2;
            int dir  = n >> 11;
            int c2   = n & 2047;
            int gate = c2 >> 9;
            int j    = c2 & 511;
            int jg   = j >> 5;
            int jj   = j & 31;
            float2 bv = *(const float2*)(bias + n);
            float2 o0 = make_float2(acc[mt][nt][0]+bv.x, acc[mt][nt][1]+bv.y);
            float2 o1 = make_float2(acc[mt][nt][2]+bv.x, acc[mt][nt][3]+bv.y);
            size_t base = (((size_t)(dir*16 + jg)*MM) + m)*128 + gate*32 + jj;
            *(float2*)&g_PRE[base]         = o0;
            *(float2*)&g_PRE[base + 8*128] = o1;   // row m+8
        }
    }
}

// ---------------- persistent LSTM scan: 128 blocks, (32 j) x (batch-quarter) tiles ----------------
// block = (dir, jg 0..15, bq 0..3). Whh slice 128 rows x 512 (128KB SMEM).
// h stage per step = 32 rows x 1KB = 32KB; fan-in = 16 producers of same (dir,bq).
__global__ __launch_bounds__(256, 1) void lstm_scan_mma(int layer)
{
    extern __shared__ char smraw[];
    bf16*  Ws   = (bf16*)smraw;                              // 128 rows x 1024B = 131072
    char*  Asm  = smraw + 131072;                            // 32 rows x 1040B = 33280
    float* zb   = (float*)(smraw + 131072 + 33280);          // [32][136] = 17408
    float* sPre = (float*)(smraw + 131072 + 33280 + 17408);  // [32][128] = 16384
    __shared__ __align__(8) unsigned long long mbars[2];     // H, PRE

    const int bid = blockIdx.x;
    const int dir = bid >> 6;
    const int rem = bid & 63;
    const int jg  = rem >> 2;          // 0..15
    const int bq  = rem & 3;           // 0..3
    const int j0  = jg << 5;
    bf16* Hbuf = layer ? (dir ? g_HB1 : g_HB0)
                       : (dir ? g_HA1 : g_HA0);
    const bf16* WH = layer ? g_WH1b : g_WH0b;
    const int tid = threadIdx.x;
    const int warp = tid>>5, lane = tid&31;
    const int wm = warp>>2, wn = warp&3;
    unsigned WsB = su32(Ws), AsB = su32(Asm), sPreB = su32(sPre);
    unsigned mbH = su32(&mbars[0]), mbP = su32(&mbars[1]);

    if (tid == 0){
        mbar_init(mbH, 1);
        mbar_init(mbP, 1);
        asm volatile("fence.proxy.async.shared::cta;" ::: "memory");
    }
    // ---- load Whh slice (128 rows x 512) once, swizzled; row n' = gate*32+jj ----
    {
        const bf16* wb = WH + (size_t)dir*2048*512;
        int rr  = tid >> 1;                 // n' 0..127
        int kc0 = (tid & 1) << 5;           // 32 chunks each
        int wrow = ((rr>>5)<<9) + j0 + (rr & 31);   // gate*512 + j0 + jj
        const bf16* gp = wb + (size_t)wrow*512;
        unsigned srw = WsB + rr*1024;
        #pragma unroll
        for (int i=0;i<32;i++){
            int kc = kc0+i;
            cp16(srw + ((kc ^ (rr&7))<<4), gp + kc*8);
        }
        cpcommit(); cpwait<0>();
    }
    __syncthreads();

    // gates map: thread -> (local b = tid>>3, 4 j's at (tid&7)*4), c in registers
    const int bl = tid>>3;             // 0..31
    const int jq = (tid&7)*4;          // 0..28
    float creg[4] = {0.f, 0.f, 0.f, 0.f};

    for (int s=0; s<TT; s++){
        const int t_out = dir ? (TT-1-s) : s;

        // ---- PRE: one contiguous 16KB bulk copy, issued pre-wait ----
        if (tid == 0){
            const float* prer = g_PRE + (((size_t)(dir*16 + jg)*MM) + (size_t)t_out*BB + bq*32)*128;
            mbar_expect(mbP, 16384u);
            bulkcp(sPreB, prer, 16384u, mbP);
        }

        float acc[4][4];
        #pragma unroll
        for (int i=0;i<4;i++)
            #pragma unroll
            for (int k=0;k<4;k++) acc[i][k]=0.f;

        if (s > 0){
            const unsigned pH = (unsigned)((s-1)&1);
            const int t_prev = dir ? (t_out+1) : (s-1);
            const bf16* hbase = Hbuf + ((size_t)t_prev*BB + bq*32)*512;

            if (tid < 64){
                // threads 0..15 poll the 16 producer flags of (dir, bq)
                if (tid < 16){
                    const unsigned* fp = &g_flags[layer][dir][bq][s-1][tid*32];
                    while (load_acq(fp) == 0u) { }
                    if (tid == 0) mbar_expect(mbH, 32768u);
                }
                bar_named(1, 64);
                // 64 threads each stage 512B (32 rows x 2 chunks)
                int row = tid >> 1, half = tid & 1;
                bulkcp(AsB + row*1040 + half*512,
                       hbase + (size_t)row*512 + half*256, 512u, mbH);
            }

            mbar_wait(mbH, pH);

            // mma M=32 x N=128 x K=512 ; warp tile 16 x 32
            #pragma unroll 4
            for (int kk=0; kk<32; kk++){
                unsigned af[4];
                {
                    int row = wm*16 + (lane&15);
                    int ch  = kk*2 + (lane>>4);
                    ldsm4(af[0],af[1],af[2],af[3], AsB + row*1040 + ch*16);
                }
                unsigned bfr[2][4];
                #pragma unroll
                for (int np=0; np<2; np++){
                    int row = wn*32 + np*16 + (lane&7) + ((lane>=16)?8:0);
                    int ch  = kk*2 + ((lane>>3)&1);
                    ldsm4(bfr[np][0],bfr[np][1],bfr[np][2],bfr[np][3],
                          WsB + row*1024 + ((ch ^ (row&7))<<4));
                }
                #pragma unroll
                for (int nt=0; nt<4; nt++)
                    mma16816(acc[nt], af, bfr[nt>>1][(nt&1)*2], bfr[nt>>1][(nt&1)*2+1]);
            }
        }
        __syncthreads();

        // ---- exchange z through smem (rows 32, stride 136 floats) ----
        {
            const int r = lane>>2, cq = (lane&3)*2;
            #pragma unroll
            for (int nt=0; nt<4; nt++){
                int mr = wm*16 + r;
                int nc = wn*32 + nt*8 + cq;
                zb[mr*136 + nc]       = acc[nt][0];
                zb[mr*136 + nc+1]     = acc[nt][1];
                zb[(mr+8)*136 + nc]   = acc[nt][2];
                zb[(mr+8)*136 + nc+1] = acc[nt][3];
            }
        }
        mbar_wait(mbP, (unsigned)(s&1));
        __syncthreads();

        // ---- gates: thread -> (bl, 4 j's), c in registers ----
        {
            const float* zr = zb + bl*136;
            const float* sp = sPre + bl*128;
            float4 zi = *(const float4*)(zr + jq);
            float4 zf = *(const float4*)(zr + 32 + jq);
            float4 zg = *(const float4*)(zr + 64 + jq);
            float4 zo = *(const float4*)(zr + 96 + jq);
            float4 pi = *(const float4*)(sp + jq);
            float4 pf = *(const float4*)(sp + 32 + jq);
            float4 pg = *(const float4*)(sp + 64 + jq);
            float4 po = *(const float4*)(sp + 96 + jq);

            float ho[4];
            float zis[4]={zi.x+pi.x, zi.y+pi.y, zi.z+pi.z, zi.w+pi.w};
            float zfs[4]={zf.x+pf.x, zf.y+pf.y, zf.z+pf.z, zf.w+pf.w};
            float zgs[4]={zg.x+pg.x, zg.y+pg.y, zg.z+pg.z, zg.w+pg.w};
            float zos[4]={zo.x+po.x, zo.y+po.y, zo.z+po.z, zo.w+po.w};
            #pragma unroll
            for (int u=0;u<4;u++){
                float fi=fsig(zis[u]), ff=fsig(zfs[u]), fg=ftanh(zgs[u]), fo=fsig(zos[u]);
                creg[u] = ff*creg[u] + fi*fg;
                ho[u] = fo*ftanh(creg[u]);
            }
            __nv_bfloat162 p0 = __floats2bfloat162_rn(ho[0],ho[1]);
            __nv_bfloat162 p1 = __floats2bfloat162_rn(ho[2],ho[3]);
            uint2 uv; uv.x = *(unsigned*)&p0; uv.y = *(unsigned*)&p1;
            *(uint2*)&Hbuf[((size_t)t_out*BB + bq*32 + bl)*512 + j0 + jq] = uv;
        }

        __syncthreads();
        if (tid==0) st_release(&g_flags[layer][dir][bq][s][jg*32], 1u);
    }
}

// ---------------- classifier emissions (h in split bf16 buffers) ----------------
__global__ void emissions_kernel(const float* __restrict__ clsW, const float* __restrict__ clsB)
{
    int warp = threadIdx.x >> 5, lane = threadIdx.x & 31;
    int row = (blockIdx.x << 3) + warp;
    const __nv_bfloat162* h20 = (const __nv_bfloat162*)(g_HB0 + (size_t)row * 512);
    const __nv_bfloat162* h21 = (const __nv_bfloat162*)(g_HB1 + (size_t)row * 512);
    float2 hv[16];
    #pragma unroll
    for (int m=0;m<8;m++)  hv[m]   = __bfloat1622float2(h20[lane + (m<<5)]);
    #pragma unroll
    for (int m=0;m<8;m++)  hv[m+8] = __bfloat1622float2(h21[lane + (m<<5)]);
    #pragma unroll
    for (int c=0;c<CC;c++) {
        const float2* w2 = (const float2*)(clsW + c*1024);
        float s = 0.f;
        #pragma unroll
        for (int m=0;m<16;m++){
            float2 wv = w2[lane + (m<<5)];
            s += hv[m].x*wv.x + hv[m].y*wv.y;
        }
        #pragma unroll
        for (int o=16;o;o>>=1) s += __shfl_xor_sync(0xffffffffu, s, o);
        if (lane==0) g_EM[(size_t)row*CC + c] = s + clsB[c];
    }
}

// ---------------- fused CRF (numerator + denominator), one warp per batch ----------------
__global__ void crf_kernel(const int* __restrict__ y, const float* __restrict__ trans,
                           const float* __restrict__ cstart, const float* __restrict__ cend)
{
    __shared__ float st[CC*CC];
    if (threadIdx.x < CC*CC) st[threadIdx.x] = trans[threadIdx.x];
    __syncthreads();

    int b = (blockIdx.x << 3) + (threadIdx.x >> 5);
    int lane = threadIdx.x & 31;
    int c = lane < CC ? lane : CC-1;
    float tcol[CC];
    #pragma unroll
    for (int i=0;i<CC;i++) tcol[i] = st[i*CC + c];

    int y0 = y[b*TT];
    int prev = y0 > 0 ? y0 : 0;
    float alpha = cstart[c] + g_EM[(size_t)b*CC + c];
    float sc = __shfl_sync(0xffffffffu, alpha, prev);
    int cnt = (y0 > -1) ? 1 : 0;

    float e_next = g_EM[((size_t)1*BB + b)*CC + c];
    int   y_next = y[b*TT + 1];

    for (int t=1;t<TT;t++) {
        float e  = e_next;
        int   yt = y_next;
        if (t+1 < TT){
            e_next = g_EM[((size_t)(t+1)*BB + b)*CC + c];
            y_next = y[b*TT + t + 1];
        }
        float av[CC]; float mx = -1e30f;
        #pragma unroll
        for (int i=0;i<CC;i++) { av[i] = __shfl_sync(0xffffffffu, alpha, i) + tcol[i]; mx = fmaxf(mx, av[i]); }
        float su = 0.f;
        #pragma unroll
        for (int i=0;i<CC;i++) su += expf(av[i]-mx);
        float nxt = mx + logf(su) + e;
        bool m = (yt > -1);
        if (m) alpha = nxt;
        int tgt = yt > 0 ? yt : 0;
        float etg = __shfl_sync(0xffffffffu, e, tgt);
        sc += (st[prev*CC + tgt] + etg) * (m ? 1.f : 0.f);
        prev = tgt;
        cnt += m ? 1 : 0;
    }
    int se = cnt - 1; if (se < 0) se = 0;
    int yl = y[b*TT + se];
    int lt = yl > 0 ? yl : 0;
    sc += cend[lt];

    float v = alpha + cend[c];
    float mx = -1e30f;
    #pragma unroll
    for (int i=0;i<CC;i++) mx = fmaxf(mx, __shfl_sync(0xffffffffu, v, i));
    float su = 0.f;
    #pragma unroll
    for (int i=0;i<CC;i++) su += expf(__shfl_sync(0xffffffffu, v, i) - mx);
    if (lane==0) g_LLH[b] = sc - (mx + logf(su));
}

// ---------------- final reduction ----------------
__global__ void final_kernel(float* __restrict__ out)
{
    int tid = threadIdx.x;
    float v = g_LLH[tid];
    #pragma unroll
    for (int o=16;o;o>>=1) v += __shfl_xor_sync(0xffffffffu, v, o);
    __shared__ float sr[4];
    if ((tid&31)==0) sr[tid>>5] = v;
    __syncthreads();
    if (tid==0) out[0] = -(sr[0]+sr[1]+sr[2]+sr[3]) / 128.0f;
}

// ---------------- launch ----------------
extern "C" void kernel_launch(void* const* d_in, const int* in_sizes, int n_in,
                              void* d_out, int out_size)
{
    const int*   x        = (const int*)  d_in[0];
    const int*   y        = (const int*)  d_in[1];
    const float* embed    = (const float*)d_in[2];
    const float* w_ih_l0  = (const float*)d_in[3];
    const float* w_hh_l0  = (const float*)d_in[4];
    const float* b_l0     = (const float*)d_in[5];
    const float* w_ih_l1  = (const float*)d_in[6];
    const float* w_hh_l1  = (const float*)d_in[7];
    const float* b_l1     = (const float*)d_in[8];
    const float* cls_w    = (const float*)d_in[9];
    const float* cls_b    = (const float*)d_in[10];
    const float* crf_start= (const float*)d_in[11];
    const float* crf_end  = (const float*)d_in[12];
    const float* crf_trans= (const float*)d_in[13];
    float* out = (float*)d_out;

    const int GEMM_SMEM = 2*(128*64)*2*2;                           // 65536 B
    const int SCAN_SMEM = 131072 + 33280 + 17408 + 16384;           // 198144 B
    cudaFuncSetAttribute(gemm_pre_mma, cudaFuncAttributeMaxDynamicSharedMemorySize, GEMM_SMEM);
    cudaFuncSetAttribute(lstm_scan_mma, cudaFuncAttributeMaxDynamicSharedMemorySize, SCAN_SMEM);

    reset_flags<<<1024, 64>>>();
    embed_kernel<<<MM, 128>>>(x, embed);
    convert_weights<<<512, 256>>>(w_ih_l0, w_hh_l0, w_ih_l1, w_hh_l1);

    gemm_pre_mma<<<dim3(32,256), 256, GEMM_SMEM>>>(0, b_l0);
    lstm_scan_mma<<<128, 256, SCAN_SMEM>>>(0);
    gemm_pre_mma<<<dim3(32,256), 256, GEMM_SMEM>>>(1, b_l1);
    lstm_scan_mma<<<128, 256, SCAN_SMEM>>>(1);

    emissions_kernel<<<4096, 256>>>(cls_w, cls_b);
    crf_kernel<<<16, 256>>>(y, crf_trans, crf_start, crf_end);
    final_kernel<<<1, 128>>>(out);
}